// round 11
// baseline (speedup 1.0000x reference)
#include <cuda_runtime.h>
#include <stdint.h>

typedef unsigned long long u64;
typedef uint32_t u32;

#define BB 2
#define KK 19
#define BKT 38
#define MM 1024
#define CC 256
#define NP 128
#define NS 128

// ---------------- device scratch ----------------
__device__ float g_x[BKT*MM*3];
__device__ float g_F1[BKT*MM*128];
__device__ float g_newxyz[BKT*NP*3];
__device__ int   g_gidx[BKT*NP*NS];
__device__ float g_feat[BKT*128*NP];
__device__ float g_W1H[128*CC];      // [o][c] tf32-hi
__device__ float g_W1L[128*CC];      // [o][c] tf32-lo
__device__ float g_W2T[128*128];     // [o][c] tf32-rounded (mma B operand)
__device__ float g_W3T[128*128];     // [o][c] tf32-rounded
__device__ float g_C1T[128*128];     // [c][o] fp32
__device__ float g_C2T[128*128];
__device__ float g_W1x[3*128];
__device__ float g_bM1[128], g_bM2[128], g_bM3[128], g_bC1[128], g_bC2[128];

// ---------------- tf32 helpers ----------------
__device__ __forceinline__ u32 tf32b(float f){
  u32 r; asm("cvt.rna.tf32.f32 %0, %1;" : "=r"(r) : "f"(f)); return r;
}
__device__ __forceinline__ float tf32r(float f){ return __uint_as_float(tf32b(f)); }

__device__ __forceinline__ void mma_tf32(float d[4], const u32 a[4], const u32 b[2]){
  asm volatile("mma.sync.aligned.m16n8k8.row.col.f32.tf32.tf32.f32 "
    "{%0,%1,%2,%3}, {%4,%5,%6,%7}, {%8,%9}, {%0,%1,%2,%3};"
    : "+f"(d[0]), "+f"(d[1]), "+f"(d[2]), "+f"(d[3])
    : "r"(a[0]), "r"(a[1]), "r"(a[2]), "r"(a[3]), "r"(b[0]), "r"(b[1]));
}

// ---------------- f32x2 helpers (k_c12 tail) ----------------
__device__ __forceinline__ u64 pk2(float a){ u64 r; asm("mov.b64 %0, {%1, %1};" : "=l"(r) : "f"(a)); return r; }
__device__ __forceinline__ void fma2(u64& d, u64 a, u64 b){ asm("fma.rn.f32x2 %0, %1, %2, %0;" : "+l"(d) : "l"(a), "l"(b)); }
__device__ __forceinline__ float2 upk(u64 v){ float2 r; asm("mov.b64 {%0, %1}, %2;" : "=f"(r.x), "=f"(r.y) : "l"(v)); return r; }
__device__ __forceinline__ void zacc8(u64 acc[8][4]){
#pragma unroll
  for (int i=0;i<8;i++)
#pragma unroll
    for (int j=0;j<4;j++) acc[i][j]=0ull;
}
#define GROW(i, av) { u64 a_=pk2(av); fma2(acc[i][0],a_,b0); fma2(acc[i][1],a_,b1); fma2(acc[i][2],a_,b2); fma2(acc[i][3],a_,b3); }
template<int KC>
__device__ __forceinline__ void gemm8x8(const float* sA, const float* sB, u64 acc[8][4], int s0, int o0){
#pragma unroll 4
  for (int c = 0; c < KC; c++){
    float4 a0 = *(const float4*)(sA + c*128 + s0);
    float4 a1 = *(const float4*)(sA + c*128 + s0 + 4);
    const u64* bp = (const u64*)(sB + c*128 + o0);
    u64 b0=bp[0], b1=bp[1], b2=bp[2], b3=bp[3];
    GROW(0,a0.x) GROW(1,a0.y) GROW(2,a0.z) GROW(3,a0.w)
    GROW(4,a1.x) GROW(5,a1.y) GROW(6,a1.z) GROW(7,a1.w)
  }
}

__device__ __forceinline__ float d2f(float ax,float ay,float az,float bx,float by,float bz){
  float dx=__fsub_rn(ax,bx), dy=__fsub_rn(ay,by), dz=__fsub_rn(az,bz);
  return __fadd_rn(__fadd_rn(__fmul_rn(dx,dx),__fmul_rn(dy,dy)),__fmul_rn(dz,dz));
}

__device__ __forceinline__ float gpv(float g){ return __fdiv_rn(g, sqrtf(1.0f + 1e-5f)); }

// ---------------- launch 0: prep x + fold everything ----------------
// items: prep_x 116736 | W1 hi/lo 32768 | W2T 16384 | W3T 16384 | C1T 16384 | C2T 16384 | biases 640 | W1x 384
__global__ void k_prep_fold(const float* __restrict__ xyz,
                            const float* m1w, const float* m1g,
                            const float* m2w, const float* m2g,
                            const float* m3w, const float* m3g,
                            const float* c1w, const float* c1g,
                            const float* c2w, const float* c2g,
                            const float* m1b, const float* m1be,
                            const float* m2b, const float* m2be,
                            const float* m3b, const float* m3be,
                            const float* c1b, const float* c1be,
                            const float* c2b, const float* c2be){
  int i = blockIdx.x*256 + threadIdx.x;
  if (i < 116736){
    int j = i % 3, rest = i / 3;
    int m = rest % MM, bk = rest / MM;
    int b = bk / KK, k = bk % KK;
    g_x[i] = xyz[((size_t)(b*MM + m)*KK + k)*3 + j];
    return;
  } i -= 116736;
  if (i < 32768){                 // W1 hi/lo [o][c]
    int o = i>>8, c = i&255;
    float v = m1w[o*259 + 3 + c] * gpv(m1g[o]);
    float hi = tf32r(v);
    g_W1H[i] = hi;
    g_W1L[i] = tf32r(__fsub_rn(v, hi));
    return;
  } i -= 32768;
  if (i < 16384){                 // W2T [o][c] tf32
    g_W2T[i] = tf32r(m2w[i] * gpv(m2g[i>>7]));
    return;
  } i -= 16384;
  if (i < 16384){
    g_W3T[i] = tf32r(m3w[i] * gpv(m3g[i>>7]));
    return;
  } i -= 16384;
  if (i < 16384){                 // C1T [c][o]
    int c = i>>7, o = i&127;
    g_C1T[i] = c1w[o*128+c] * gpv(c1g[o]);
    return;
  } i -= 16384;
  if (i < 16384){
    int c = i>>7, o = i&127;
    g_C2T[i] = c2w[o*128+c] * gpv(c2g[o]);
    return;
  } i -= 16384;
  if (i < 640){                   // biases
    int which = i>>7, o = i&127;
    const float* b  = which==0?m1b: which==1?m2b: which==2?m3b: which==3?c1b:c2b;
    const float* g  = which==0?m1g: which==1?m2g: which==2?m3g: which==3?c1g:c2g;
    const float* be = which==0?m1be:which==1?m2be:which==2?m3be:which==3?c1be:c2be;
    float* dst = which==0?g_bM1: which==1?g_bM2: which==2?g_bM3: which==3?g_bC1:g_bC2;
    dst[o] = b[o]*gpv(g[o]) + be[o];
    return;
  } i -= 640;
  if (i < 384){                   // W1x
    int j = i>>7, o = i&127;
    g_W1x[i] = m1w[o*259 + j] * gpv(m1g[o]);
  }
}

// ---------------- launch 1: fused FPS (blocks 0..37) + F1-mma (blocks 38..341) ----
#define LDM 136   // A smem stride (conflict-free frag reads)
#define LDWF 68   // W smem stride

__device__ void fps_body(float* __restrict__ outAgg){
  int bk = blockIdx.x, t = threadIdx.x;
  const float* xb = g_x + bk*MM*3;
  float px[4], py[4], pz[4], dist[4];
#pragma unroll
  for (int j = 0; j < 4; j++){
    int m = t + 256*j;
    px[j] = xb[m*3]; py[j] = xb[m*3+1]; pz[j] = xb[m*3+2];
    dist[j] = 1e10f;
  }
  __shared__ float sc[3]; __shared__ float sv[8]; __shared__ int si_[8]; __shared__ int sfar;
  if (t == 0) sfar = 0;
  __syncthreads();
  int lane = t & 31, wp = t >> 5;
  for (int i = 0; i < NP; i++){
    if (t == 0){
      int f = sfar;
      float cx = xb[f*3], cy = xb[f*3+1], cz = xb[f*3+2];
      sc[0]=cx; sc[1]=cy; sc[2]=cz;
      float* nz = g_newxyz + (bk*NP+i)*3; nz[0]=cx; nz[1]=cy; nz[2]=cz;
      float* oa = outAgg + (bk*NP+i)*3;   oa[0]=cx; oa[1]=cy; oa[2]=cz;
    }
    __syncthreads();
    float cx = sc[0], cy = sc[1], cz = sc[2];
    float v = -1.f; int ix = 0;
#pragma unroll
    for (int j = 0; j < 4; j++){
      float d = d2f(px[j],py[j],pz[j], cx,cy,cz);
      dist[j] = fminf(dist[j], d);
      if (dist[j] > v){ v = dist[j]; ix = t + 256*j; }   // ascending j => first-index tie-break
    }
#pragma unroll
    for (int off=16; off; off>>=1){
      float ov = __shfl_down_sync(0xffffffffu, v, off);
      int   oi = __shfl_down_sync(0xffffffffu, ix, off);
      if (ov > v || (ov == v && oi < ix)){ v = ov; ix = oi; }
    }
    if (lane == 0){ sv[wp] = v; si_[wp] = ix; }
    __syncthreads();
    if (t < 8){
      v = sv[t]; ix = si_[t];
#pragma unroll
      for (int off=4; off; off>>=1){
        float ov = __shfl_down_sync(0xffu, v, off);
        int   oi = __shfl_down_sync(0xffu, ix, off);
        if (ov > v || (ov == v && oi < ix)){ v = ov; ix = oi; }
      }
      if (t == 0) sfar = ix;
    }
    __syncthreads();
  }
}

__device__ void f1_body(const float* __restrict__ features, float* sm){
  float* sF  = sm;                    // [c 64][m 128] stride LDM
  float* sWh = sm + 64*LDM;           // [o 128][c 64] stride LDWF
  float* sWl = sWh + 128*LDWF;
  int fb = blockIdx.x - BKT;
  int bk = fb >> 3, mb = (fb & 7)*128;
  int b = bk / KK, k = bk % KK;
  int t = threadIdx.x;
  int w = t >> 5, lane = t & 31;
  int gid = lane >> 2, tq = lane & 3;
  int m0 = (w & 3)*32, n0 = (w >> 2)*64;

  float acc[2][8][4];
#pragma unroll
  for (int mt=0;mt<2;mt++)
#pragma unroll
    for (int nt=0;nt<8;nt++)
#pragma unroll
      for (int j=0;j<4;j++) acc[mt][nt][j] = 0.f;

  for (int c0 = 0; c0 < CC; c0 += 64){
    // A tile: [ci][m] coalesced along m
#pragma unroll
    for (int r = 0; r < 8; r++){
      int e4 = r*256 + t;            // 2048 float4
      int ci = e4 >> 5, q = e4 & 31;
      *(float4*)(sF + ci*LDM + q*4) =
        *(const float4*)(features + ((size_t)(b*CC + c0 + ci)*KK + k)*MM + mb + q*4);
    }
    // W hi/lo tiles: [o][c-chunk]
#pragma unroll
    for (int r = 0; r < 8; r++){
      int e4 = r*256 + t;            // 2048 float4
      int o = e4 >> 4, q = e4 & 15;
      *(float4*)(sWh + o*LDWF + q*4) = *(const float4*)(g_W1H + o*CC + c0 + q*4);
      *(float4*)(sWl + o*LDWF + q*4) = *(const float4*)(g_W1L + o*CC + c0 + q*4);
    }
    __syncthreads();
#pragma unroll
    for (int ks = 0; ks < 8; ks++){
      int kc = ks*8;
      u32 ah[2][4], al[2][4], bh[8][2], bl[8][2];
#pragma unroll
      for (int mt = 0; mt < 2; mt++){
        int r0 = m0 + mt*16 + gid;
        float f0 = sF[(kc+tq)*LDM + r0];
        float f1 = sF[(kc+tq)*LDM + r0 + 8];
        float f2 = sF[(kc+tq+4)*LDM + r0];
        float f3 = sF[(kc+tq+4)*LDM + r0 + 8];
        ah[mt][0]=tf32b(f0); al[mt][0]=tf32b(__fsub_rn(f0,__uint_as_float(ah[mt][0])));
        ah[mt][1]=tf32b(f1); al[mt][1]=tf32b(__fsub_rn(f1,__uint_as_float(ah[mt][1])));
        ah[mt][2]=tf32b(f2); al[mt][2]=tf32b(__fsub_rn(f2,__uint_as_float(ah[mt][2])));
        ah[mt][3]=tf32b(f3); al[mt][3]=tf32b(__fsub_rn(f3,__uint_as_float(ah[mt][3])));
      }
      const u32* Wha = (const u32*)sWh + (n0 + gid)*LDWF + tq;
      const u32* Wla = (const u32*)sWl + (n0 + gid)*LDWF + tq;
#pragma unroll
      for (int nt = 0; nt < 8; nt++){
        bh[nt][0] = Wha[(nt*8)*LDWF + kc]; bh[nt][1] = Wha[(nt*8)*LDWF + kc + 4];
        bl[nt][0] = Wla[(nt*8)*LDWF + kc]; bl[nt][1] = Wla[(nt*8)*LDWF + kc + 4];
      }
#pragma unroll
      for (int mt = 0; mt < 2; mt++)
#pragma unroll
        for (int nt = 0; nt < 8; nt++){
          mma_tf32(acc[mt][nt], ah[mt], bh[nt]);
          mma_tf32(acc[mt][nt], al[mt], bh[nt]);
          mma_tf32(acc[mt][nt], ah[mt], bl[nt]);
        }
    }
    __syncthreads();
  }
  // write F1: row = point, col = o
#pragma unroll
  for (int mt = 0; mt < 2; mt++){
    size_t r0 = (size_t)bk*MM + mb + m0 + mt*16 + gid;
#pragma unroll
    for (int nt = 0; nt < 8; nt++){
      int c0 = n0 + nt*8 + 2*tq;
      float2 v;
      v.x = acc[mt][nt][0]; v.y = acc[mt][nt][1];
      *(float2*)(g_F1 + r0*128 + c0) = v;
      v.x = acc[mt][nt][2]; v.y = acc[mt][nt][3];
      *(float2*)(g_F1 + (r0+8)*128 + c0) = v;
    }
  }
}

__global__ __launch_bounds__(256, 2) void k_fps_f1(const float* __restrict__ features,
                                                   float* __restrict__ outAgg){
  extern __shared__ float smdyn[];
  if (blockIdx.x < BKT) fps_body(outAgg);
  else                  f1_body(features, smdyn);
}

// ---------------- launch 2: ball query ----------------
__global__ void k_ball(){
  int w = (blockIdx.x*blockDim.x + threadIdx.x) >> 5;
  int lane = threadIdx.x & 31;
  if (w >= BKT*NP) return;
  int bk = w / NP;
  const float* ctr = g_newxyz + w*3;
  float cx=ctr[0], cy=ctr[1], cz=ctr[2];
  const float R2 = (float)(0.15*0.15);
  int base = w*NS;
  int cnt = 0, first = 0;
  for (int ch = 0; ch < MM/32; ch++){
    int m = ch*32 + lane;
    const float* xp = g_x + (bk*MM + m)*3;
    float d = d2f(cx,cy,cz, xp[0],xp[1],xp[2]);
    unsigned mask = __ballot_sync(0xffffffffu, d < R2);
    if (cnt == 0 && mask) first = ch*32 + __ffs(mask) - 1;
    int pos = cnt + __popc(mask & ((1u<<lane)-1u));
    if ((d < R2) && pos < NS) g_gidx[base + pos] = m;
    cnt += __popc(mask);
    if (cnt >= NS) break;
  }
  for (int j = cnt + lane; j < NS; j += 32) g_gidx[base + j] = first;
}

// ---------------- launch 3 (PROFILED): group (mma.sync tf32) ----------------
#define LDW 132
__global__ __launch_bounds__(256, 1) void k_group(float* __restrict__ outFeat){
  extern __shared__ float sm[];
  float* H  = sm;               // [s*LDW + c]
  float* W2 = sm + 128*LDW;
  float* W3 = sm + 2*128*LDW;
  __shared__ int   sIdx[NS];
  __shared__ float sCtr[3];
  __shared__ float sWx[3*128];
  __shared__ float sB1[128], sB2[128];

  int bk = blockIdx.y, p = blockIdx.x, t = threadIdx.x;
  int w = t >> 5, lane = t & 31;
  int gid = lane >> 2, tq = lane & 3;
  int m0 = (w & 3)*32, n0 = (w >> 2)*64;

  int gp_ = bk*NP + p;
  if (t < NS) sIdx[t] = g_gidx[gp_*NS + t];
  if (t < 3)  sCtr[t] = g_newxyz[gp_*3 + t];
  if (t < 128){
    sWx[t]=g_W1x[t]; sWx[128+t]=g_W1x[128+t]; sWx[256+t]=g_W1x[256+t];
    sB1[t]=g_bM1[t]; sB2[t]=g_bM2[t];
  }
#pragma unroll
  for (int r = 0; r < 16; r++){
    int i = r*256 + t;
    int row = i >> 5, q = i & 31;
    ((float4*)(W2 + row*LDW))[q] = ((const float4*)g_W2T)[i];
    ((float4*)(W3 + row*LDW))[q] = ((const float4*)g_W3T)[i];
  }
  __syncthreads();

  // ---- layer 1 build: H[s][c] tf32-rounded ----
  {
    int s = t >> 1, ob = (t & 1)*64;
    int m = sIdx[s];
    const float* xp = g_x + (bk*MM + m)*3;
    float gx = __fdiv_rn(__fsub_rn(xp[0], sCtr[0]), 0.15f);
    float gy = __fdiv_rn(__fsub_rn(xp[1], sCtr[1]), 0.15f);
    float gz = __fdiv_rn(__fsub_rn(xp[2], sCtr[2]), 0.15f);
    const float4* fp = (const float4*)(g_F1 + ((size_t)bk*MM + m)*128 + ob);
#pragma unroll 4
    for (int j4 = 0; j4 < 16; j4++){
      float4 fv = fp[j4];
      int o = ob + j4*4;
      float4 u;
      u.x = tf32r(fmaxf(fv.x + sWx[o]*gx   + sWx[128+o]*gy   + sWx[256+o]*gz   + sB1[o],   0.f));
      u.y = tf32r(fmaxf(fv.y + sWx[o+1]*gx + sWx[128+o+1]*gy + sWx[256+o+1]*gz + sB1[o+1], 0.f));
      u.z = tf32r(fmaxf(fv.z + sWx[o+2]*gx + sWx[128+o+2]*gy + sWx[256+o+2]*gz + sB1[o+2], 0.f));
      u.w = tf32r(fmaxf(fv.w + sWx[o+3]*gx + sWx[128+o+3]*gy + sWx[256+o+3]*gz + sB1[o+3], 0.f));
      *(float4*)(H + s*LDW + o) = u;
    }
  }
  __syncthreads();

  float acc[2][8][4];
  const u32* Ha = (const u32*)H + (m0 + gid)*LDW + tq;
  const u32* W2a = (const u32*)W2 + (n0 + gid)*LDW + tq;
  const u32* W3a = (const u32*)W3 + (n0 + gid)*LDW + tq;

  // ---- GEMM 1 ----
#pragma unroll
  for (int mt=0;mt<2;mt++)
#pragma unroll
    for (int nt=0;nt<8;nt++)
#pragma unroll
      for (int j=0;j<4;j++) acc[mt][nt][j] = 0.f;
#pragma unroll 2
  for (int ks = 0; ks < 16; ks++){
    int kc = ks*8;
    u32 a[2][4], b[8][2];
#pragma unroll
    for (int mt = 0; mt < 2; mt++){
      a[mt][0] = Ha[(mt*16)*LDW + kc];
      a[mt][1] = Ha[(mt*16+8)*LDW + kc];
      a[mt][2] = Ha[(mt*16)*LDW + kc + 4];
      a[mt][3] = Ha[(mt*16+8)*LDW + kc + 4];
    }
#pragma unroll
    for (int nt = 0; nt < 8; nt++){
      b[nt][0] = W2a[(nt*8)*LDW + kc];
      b[nt][1] = W2a[(nt*8)*LDW + kc + 4];
    }
#pragma unroll
    for (int mt = 0; mt < 2; mt++)
#pragma unroll
      for (int nt = 0; nt < 8; nt++)
        mma_tf32(acc[mt][nt], a[mt], b[nt]);
  }
  __syncthreads();

  // ---- epilogue: H' = tf32(relu(D1 + b2)) ----
#pragma unroll
  for (int mt = 0; mt < 2; mt++){
    int r0 = m0 + mt*16 + gid;
#pragma unroll
    for (int nt = 0; nt < 8; nt++){
      int c0 = n0 + nt*8 + 2*tq;
      float b0v = sB2[c0], b1v = sB2[c0+1];
      float2 v;
      v.x = tf32r(fmaxf(acc[mt][nt][0] + b0v, 0.f));
      v.y = tf32r(fmaxf(acc[mt][nt][1] + b1v, 0.f));
      *(float2*)(H + r0*LDW + c0) = v;
      v.x = tf32r(fmaxf(acc[mt][nt][2] + b0v, 0.f));
      v.y = tf32r(fmaxf(acc[mt][nt][3] + b1v, 0.f));
      *(float2*)(H + (r0+8)*LDW + c0) = v;
    }
  }
  __syncthreads();

  // ---- GEMM 2 ----
#pragma unroll
  for (int mt=0;mt<2;mt++)
#pragma unroll
    for (int nt=0;nt<8;nt++)
#pragma unroll
      for (int j=0;j<4;j++) acc[mt][nt][j] = 0.f;
#pragma unroll 2
  for (int ks = 0; ks < 16; ks++){
    int kc = ks*8;
    u32 a[2][4], b[8][2];
#pragma unroll
    for (int mt = 0; mt < 2; mt++){
      a[mt][0] = Ha[(mt*16)*LDW + kc];
      a[mt][1] = Ha[(mt*16+8)*LDW + kc];
      a[mt][2] = Ha[(mt*16)*LDW + kc + 4];
      a[mt][3] = Ha[(mt*16+8)*LDW + kc + 4];
    }
#pragma unroll
    for (int nt = 0; nt < 8; nt++){
      b[nt][0] = W3a[(nt*8)*LDW + kc];
      b[nt][1] = W3a[(nt*8)*LDW + kc + 4];
    }
#pragma unroll
    for (int mt = 0; mt < 2; mt++)
#pragma unroll
      for (int nt = 0; nt < 8; nt++)
        mma_tf32(acc[mt][nt], a[mt], b[nt]);
  }

  // ---- maxpool over s ----
  float cm[8][2];
#pragma unroll
  for (int nt = 0; nt < 8; nt++){
    cm[nt][0] = fmaxf(fmaxf(acc[0][nt][0], acc[0][nt][2]), fmaxf(acc[1][nt][0], acc[1][nt][2]));
    cm[nt][1] = fmaxf(fmaxf(acc[0][nt][1], acc[0][nt][3]), fmaxf(acc[1][nt][1], acc[1][nt][3]));
  }
#pragma unroll
  for (int off = 4; off < 32; off <<= 1){
#pragma unroll
    for (int nt = 0; nt < 8; nt++){
      cm[nt][0] = fmaxf(cm[nt][0], __shfl_xor_sync(0xffffffffu, cm[nt][0], off));
      cm[nt][1] = fmaxf(cm[nt][1], __shfl_xor_sync(0xffffffffu, cm[nt][1], off));
    }
  }
  float* psm = W2;
  if (gid == 0){
#pragma unroll
    for (int nt = 0; nt < 8; nt++){
      psm[(w & 3)*128 + n0 + nt*8 + 2*tq]     = cm[nt][0];
      psm[(w & 3)*128 + n0 + nt*8 + 2*tq + 1] = cm[nt][1];
    }
  }
  __syncthreads();
  if (t < 128){
    float mx = fmaxf(fmaxf(psm[t], psm[128+t]), fmaxf(psm[256+t], psm[384+t]));
    float res = fmaxf(mx + g_bM3[t], 0.f);
    int fo = (bk*128 + t)*NP + p;
    g_feat[fo] = res;
    outFeat[fo] = res;
  }
}

// ---------------- launch 4: c1 + c2 + head ----------------
__global__ __launch_bounds__(256) void k_c12h(const float* __restrict__ opw,
                                              const float* __restrict__ opb,
                                              float* __restrict__ outScores){
  extern __shared__ float sm[];
  float* sH = sm;
  float* sW = sm + 16384;
  __shared__ float sOp[5*128]; __shared__ float sOb[5];
  int bk = blockIdx.x, t = threadIdx.x;
  int k = bk % KK;
  for (int i = t; i < 640; i += 256) sOp[i] = opw[k*640 + i];
  if (t < 5) sOb[t] = opb[k*5 + t];
#pragma unroll
  for (int r = 0; r < 16; r++){
    ((float4*)sH)[r*256 + t] = ((const float4*)(g_feat + bk*16384))[r*256 + t];
    ((float4*)sW)[r*256 + t] = ((const float4*)g_C1T)[r*256 + t];
  }
  __syncthreads();
  int s0 = (t & 15)*8, o0 = (t >> 4)*8;
  u64 acc[8][4]; zacc8(acc);
  gemm8x8<128>(sH, sW, acc, s0, o0);
  float2 bb[4];
#pragma unroll
  for (int j = 0; j < 4; j++) bb[j] = *(const float2*)(g_bC1 + o0 + 2*j);
  __syncthreads();
#pragma unroll
  for (int si = 0; si < 8; si++)
#pragma unroll
    for (int j = 0; j < 4; j++){
      float2 v = upk(acc[si][j]);
      sH[(o0+2*j)*128 + s0+si]   = fmaxf(v.x + bb[j].x, 0.f);
      sH[(o0+2*j+1)*128 + s0+si] = fmaxf(v.y + bb[j].y, 0.f);
    }
#pragma unroll
  for (int r = 0; r < 16; r++) ((float4*)sW)[r*256 + t] = ((const float4*)g_C2T)[r*256 + t];
  __syncthreads();
  zacc8(acc);
  gemm8x8<128>(sH, sW, acc, s0, o0);
#pragma unroll
  for (int j = 0; j < 4; j++) bb[j] = *(const float2*)(g_bC2 + o0 + 2*j);
  __syncthreads();
#pragma unroll
  for (int si = 0; si < 8; si++)
#pragma unroll
    for (int j = 0; j < 4; j++){
      float2 v = upk(acc[si][j]);
      sH[(o0+2*j)*128 + s0+si]   = fmaxf(v.x + bb[j].x, 0.f);
      sH[(o0+2*j+1)*128 + s0+si] = fmaxf(v.y + bb[j].y, 0.f);
    }
  __syncthreads();
  // head: net in sH[o][p]
  if (t < 128){
    float a0=0,a1=0,a2=0,a3=0,a4=0;
#pragma unroll 4
    for (int c = 0; c < 128; c++){
      float nv = sH[c*128 + t];
      a0 += sOp[c]*nv; a1 += sOp[128+c]*nv; a2 += sOp[256+c]*nv; a3 += sOp[384+c]*nv; a4 += sOp[512+c]*nv;
    }
    a0+=sOb[0]; a1+=sOb[1]; a2+=sOb[2]; a3+=sOb[3]; a4+=sOb[4];
    const float* nz = g_newxyz + (bk*NP + t)*3;
    float* o = outScores + (bk*NP + t)*5;
    o[0]=a0; o[1]=a1; o[2]=nz[0]+a2; o[3]=nz[1]+a3; o[4]=nz[2]+a4;
  }
}

// ---------------- launcher ----------------
extern "C" void kernel_launch(void* const* d_in, const int* in_sizes, int n_in,
                              void* d_out, int out_size){
  (void)in_sizes; (void)n_in; (void)out_size;
  const float* xyz  = (const float*)d_in[0];
  const float* feats= (const float*)d_in[1];
  const float* m1_w = (const float*)d_in[2];
  const float* m1_b = (const float*)d_in[3];
  const float* m1_g = (const float*)d_in[4];
  const float* m1_be= (const float*)d_in[5];
  const float* m2_w = (const float*)d_in[6];
  const float* m2_b = (const float*)d_in[7];
  const float* m2_g = (const float*)d_in[8];
  const float* m2_be= (const float*)d_in[9];
  const float* m3_w = (const float*)d_in[10];
  const float* m3_b = (const float*)d_in[11];
  const float* m3_g = (const float*)d_in[12];
  const float* m3_be= (const float*)d_in[13];
  const float* c1_w = (const float*)d_in[14];
  const float* c1_b = (const float*)d_in[15];
  const float* c1_g = (const float*)d_in[16];
  const float* c1_be= (const float*)d_in[17];
  const float* c2_w = (const float*)d_in[18];
  const float* c2_b = (const float*)d_in[19];
  const float* c2_g = (const float*)d_in[20];
  const float* c2_be= (const float*)d_in[21];
  const float* op_w = (const float*)d_in[22];
  const float* op_b = (const float*)d_in[23];

  float* out = (float*)d_out;
  float* outScores = out;                 // 38*128*5
  float* outAgg    = out + 24320;         // 38*128*3
  float* outFeat   = out + 38912;         // 38*128*128

  const int F1_SMEM = (64*LDM + 2*128*LDWF)*4;   // 104448
  cudaFuncSetAttribute(k_fps_f1, cudaFuncAttributeMaxDynamicSharedMemorySize, F1_SMEM);
  cudaFuncSetAttribute(k_group,  cudaFuncAttributeMaxDynamicSharedMemorySize, 202752);
  cudaFuncSetAttribute(k_c12h,   cudaFuncAttributeMaxDynamicSharedMemorySize, 131072);

  k_prep_fold<<<844, 256>>>(xyz, m1_w, m1_g, m2_w, m2_g,               // 0
      m3_w, m3_g, c1_w, c1_g, c2_w, c2_g,
      m1_b, m1_be, m2_b, m2_be, m3_b, m3_be, c1_b, c1_be, c2_b, c2_be);
  k_fps_f1<<<BKT + BKT*8, 256, F1_SMEM>>>(feats, outAgg);              // 1
  k_ball<<<(BKT*NP*32 + 255)/256, 256>>>();                            // 2
  k_group<<<dim3(NP, BKT), 256, 202752>>>(outFeat);                    // 3 <- profiled
  k_c12h<<<BKT, 256, 131072>>>(op_w, op_b, outScores);                 // 4
}

// round 12
// speedup vs baseline: 1.1448x; 1.1448x over previous
#include <cuda_runtime.h>
#include <stdint.h>

typedef unsigned long long u64;
typedef uint32_t u32;

#define BB 2
#define KK 19
#define BKT 38
#define MM 1024
#define CC 256
#define NP 128
#define NS 128

// ---------------- device scratch ----------------
__device__ float g_x[BKT*MM*3];
__device__ float g_F1[BKT*MM*128];
__device__ float g_newxyz[BKT*NP*3];
__device__ int   g_gidx[BKT*NP*NS];
__device__ float g_feat[BKT*128*NP];
__device__ float g_W1T[CC*128];      // [c][o] fp32 (FFMA2 k_f1)
__device__ float g_W2F[128*136];     // frag-major tf32 (row stride 136 floats = 68 u64)
__device__ float g_W3F[128*136];
__device__ float g_C1T[128*128];     // [c][o] fp32
__device__ float g_C2T[128*128];
__device__ float g_W1x[3*128];
__device__ float g_bM1[128], g_bM2[128], g_bM3[128], g_bC1[128], g_bC2[128];

// ---------------- tf32 helpers ----------------
__device__ __forceinline__ u32 tf32b(float f){
  u32 r; asm("cvt.rna.tf32.f32 %0, %1;" : "=r"(r) : "f"(f)); return r;
}
__device__ __forceinline__ float tf32r(float f){ return __uint_as_float(tf32b(f)); }

__device__ __forceinline__ void mma_tf32(float d[4], const u32 a[4], const u32 b[2]){
  asm volatile("mma.sync.aligned.m16n8k8.row.col.f32.tf32.tf32.f32 "
    "{%0,%1,%2,%3}, {%4,%5,%6,%7}, {%8,%9}, {%0,%1,%2,%3};"
    : "+f"(d[0]), "+f"(d[1]), "+f"(d[2]), "+f"(d[3])
    : "r"(a[0]), "r"(a[1]), "r"(a[2]), "r"(a[3]), "r"(b[0]), "r"(b[1]));
}

// ---------------- f32x2 helpers ----------------
__device__ __forceinline__ u64 pk2(float a){ u64 r; asm("mov.b64 %0, {%1, %1};" : "=l"(r) : "f"(a)); return r; }
__device__ __forceinline__ void fma2(u64& d, u64 a, u64 b){ asm("fma.rn.f32x2 %0, %1, %2, %0;" : "+l"(d) : "l"(a), "l"(b)); }
__device__ __forceinline__ float2 upk(u64 v){ float2 r; asm("mov.b64 {%0, %1}, %2;" : "=f"(r.x), "=f"(r.y) : "l"(v)); return r; }
__device__ __forceinline__ void zacc8(u64 acc[8][4]){
#pragma unroll
  for (int i=0;i<8;i++)
#pragma unroll
    for (int j=0;j<4;j++) acc[i][j]=0ull;
}
#define GROW(i, av) { u64 a_=pk2(av); fma2(acc[i][0],a_,b0); fma2(acc[i][1],a_,b1); fma2(acc[i][2],a_,b2); fma2(acc[i][3],a_,b3); }
template<int KC>
__device__ __forceinline__ void gemm8x8(const float* sA, const float* sB, u64 acc[8][4], int s0, int o0){
#pragma unroll 4
  for (int c = 0; c < KC; c++){
    float4 a0 = *(const float4*)(sA + c*128 + s0);
    float4 a1 = *(const float4*)(sA + c*128 + s0 + 4);
    const u64* bp = (const u64*)(sB + c*128 + o0);
    u64 b0=bp[0], b1=bp[1], b2=bp[2], b3=bp[3];
    GROW(0,a0.x) GROW(1,a0.y) GROW(2,a0.z) GROW(3,a0.w)
    GROW(4,a1.x) GROW(5,a1.y) GROW(6,a1.z) GROW(7,a1.w)
  }
}

__device__ __forceinline__ float d2f(float ax,float ay,float az,float bx,float by,float bz){
  float dx=__fsub_rn(ax,bx), dy=__fsub_rn(ay,by), dz=__fsub_rn(az,bz);
  return __fadd_rn(__fadd_rn(__fmul_rn(dx,dx),__fmul_rn(dy,dy)),__fmul_rn(dz,dz));
}
__device__ __forceinline__ float gpv(float g){ return __fdiv_rn(g, sqrtf(1.0f + 1e-5f)); }

// ---------------- launch 0: prep x + fold everything ----------------
// prep_x 116736 | W1T 32768 | W2F 16384 | W3F 16384 | C1T 16384 | C2T 16384 | bias 640 | W1x 384
__global__ void k_prep_fold(const float* __restrict__ xyz,
                            const float* m1w, const float* m1g,
                            const float* m2w, const float* m2g,
                            const float* m3w, const float* m3g,
                            const float* c1w, const float* c1g,
                            const float* c2w, const float* c2g,
                            const float* m1b, const float* m1be,
                            const float* m2b, const float* m2be,
                            const float* m3b, const float* m3be,
                            const float* c1b, const float* c1be,
                            const float* c2b, const float* c2be){
  int i = blockIdx.x*256 + threadIdx.x;
  if (i < 116736){
    int j = i % 3, rest = i / 3;
    int m = rest % MM, bk = rest / MM;
    int b = bk / KK, k = bk % KK;
    g_x[i] = xyz[((size_t)(b*MM + m)*KK + k)*3 + j];
    return;
  } i -= 116736;
  if (i < 32768){                 // W1T [c][o]
    int c = i>>7, o = i&127;
    g_W1T[i] = m1w[o*259 + 3 + c] * gpv(m1g[o]);
    return;
  } i -= 32768;
  if (i < 16384){                 // W2F frag-major: dest (r, d)
    int r = i>>7, d = i&127;
    int ks = d>>3, q = d&7, tq = q>>1, h = q&1;
    int col = ks*8 + tq + 4*h;
    g_W2F[r*136 + d] = tf32r(m2w[r*128 + col] * gpv(m2g[r]));
    return;
  } i -= 16384;
  if (i < 16384){
    int r = i>>7, d = i&127;
    int ks = d>>3, q = d&7, tq = q>>1, h = q&1;
    int col = ks*8 + tq + 4*h;
    g_W3F[r*136 + d] = tf32r(m3w[r*128 + col] * gpv(m3g[r]));
    return;
  } i -= 16384;
  if (i < 16384){                 // C1T [c][o]
    int c = i>>7, o = i&127;
    g_C1T[i] = c1w[o*128+c] * gpv(c1g[o]);
    return;
  } i -= 16384;
  if (i < 16384){
    int c = i>>7, o = i&127;
    g_C2T[i] = c2w[o*128+c] * gpv(c2g[o]);
    return;
  } i -= 16384;
  if (i < 640){
    int which = i>>7, o = i&127;
    const float* b  = which==0?m1b: which==1?m2b: which==2?m3b: which==3?c1b:c2b;
    const float* g  = which==0?m1g: which==1?m2g: which==2?m3g: which==3?c1g:c2g;
    const float* be = which==0?m1be:which==1?m2be:which==2?m3be:which==3?c1be:c2be;
    float* dst = which==0?g_bM1: which==1?g_bM2: which==2?g_bM3: which==3?g_bC1:g_bC2;
    dst[o] = b[o]*gpv(g[o]) + be[o];
    return;
  } i -= 640;
  if (i < 384){
    int j = i>>7, o = i&127;
    g_W1x[i] = m1w[o*259 + j] * gpv(m1g[o]);
  }
}

// ---------------- launch 1: FPS (1024 threads, proven) ----------------
__global__ __launch_bounds__(1024) void k_fps(float* __restrict__ outAgg){
  int bk = blockIdx.x, t = threadIdx.x;
  const float* xb = g_x + bk*MM*3;
  float px = xb[t*3], py = xb[t*3+1], pz = xb[t*3+2];
  float dist = 1e10f;
  __shared__ float sc[3]; __shared__ float sv[32]; __shared__ int sw_[32]; __shared__ int sfar;
  if (t == 0) sfar = 0;
  __syncthreads();
  int lane = t & 31, wp = t >> 5;
  for (int i = 0; i < NP; i++){
    if (t == 0){
      int f = sfar;
      float cx = xb[f*3], cy = xb[f*3+1], cz = xb[f*3+2];
      sc[0]=cx; sc[1]=cy; sc[2]=cz;
      float* nz = g_newxyz + (bk*NP+i)*3; nz[0]=cx; nz[1]=cy; nz[2]=cz;
      float* oa = outAgg + (bk*NP+i)*3;   oa[0]=cx; oa[1]=cy; oa[2]=cz;
    }
    __syncthreads();
    float d = d2f(px,py,pz, sc[0],sc[1],sc[2]);
    dist = fminf(dist, d);
    float v = dist; int ix = t;
#pragma unroll
    for (int off=16; off; off>>=1){
      float ov = __shfl_down_sync(0xffffffffu, v, off);
      int   oi = __shfl_down_sync(0xffffffffu, ix, off);
      if (ov > v || (ov == v && oi < ix)){ v = ov; ix = oi; }
    }
    if (lane == 0){ sv[wp] = v; sw_[wp] = ix; }
    __syncthreads();
    if (t < 32){
      v = sv[t]; ix = sw_[t];
#pragma unroll
      for (int off=16; off; off>>=1){
        float ov = __shfl_down_sync(0xffffffffu, v, off);
        int   oi = __shfl_down_sync(0xffffffffu, ix, off);
        if (ov > v || (ov == v && oi < ix)){ v = ov; ix = oi; }
      }
      if (t == 0) sfar = ix;
    }
    __syncthreads();
  }
}

// ---------------- launch 2: fused ball (blocks 0..607) + F1 (blocks 608..911) ----
__device__ void ball_body(){
  int w = blockIdx.x*8 + (threadIdx.x >> 5);
  int lane = threadIdx.x & 31;
  int bk = w / NP;
  const float* ctr = g_newxyz + w*3;
  float cx=ctr[0], cy=ctr[1], cz=ctr[2];
  const float R2 = (float)(0.15*0.15);
  int base = w*NS;
  int cnt = 0, first = 0;
  for (int ch = 0; ch < MM/32; ch++){
    int m = ch*32 + lane;
    const float* xp = g_x + (bk*MM + m)*3;
    float d = d2f(cx,cy,cz, xp[0],xp[1],xp[2]);
    unsigned mask = __ballot_sync(0xffffffffu, d < R2);
    if (cnt == 0 && mask) first = ch*32 + __ffs(mask) - 1;
    int pos = cnt + __popc(mask & ((1u<<lane)-1u));
    if ((d < R2) && pos < NS) g_gidx[base + pos] = m;
    cnt += __popc(mask);
    if (cnt >= NS) break;
  }
  for (int j = cnt + lane; j < NS; j += 32) g_gidx[base + j] = first;
}

__device__ void f1_body(const float* __restrict__ features, float* sm){
  float* sF = sm;
  float* sW = sm + 64*128;
  int fb = blockIdx.x - 608;
  int bk = fb >> 3, mb = (fb & 7)*128;
  int b = bk / KK, k = bk % KK;
  int t = threadIdx.x;
  int s0 = (t & 15)*8, o0 = (t >> 4)*8;
  u64 acc[8][4]; zacc8(acc);
  for (int c0 = 0; c0 < CC; c0 += 64){
#pragma unroll
    for (int r = 0; r < 8; r++){
      int e4 = r*256 + t;
      int ci = e4 >> 5, mi4 = e4 & 31;
      ((float4*)sF)[e4] = *(const float4*)(features + ((size_t)(b*CC + c0 + ci)*KK + k)*MM + mb + mi4*4);
    }
#pragma unroll
    for (int r = 0; r < 8; r++){
      int e4 = r*256 + t;
      ((float4*)sW)[e4] = ((const float4*)(g_W1T + c0*128))[e4];
    }
    __syncthreads();
    gemm8x8<64>(sF, sW, acc, s0, o0);
    __syncthreads();
  }
#pragma unroll
  for (int si = 0; si < 8; si++){
    size_t row = (size_t)bk*MM + mb + s0 + si;
#pragma unroll
    for (int j = 0; j < 4; j++)
      *(float2*)(g_F1 + row*128 + o0 + 2*j) = upk(acc[si][j]);
  }
}

__global__ __launch_bounds__(256) void k_ball_f1(const float* __restrict__ features){
  extern __shared__ float smdyn[];
  if (blockIdx.x < 608) ball_body();
  else                  f1_body(features, smdyn);
}

// ---------------- launch 3 (PROFILED): group, 512 threads, frag-major B ----------------
#define LDW 132
#define WST 68   // u64 row stride for frag-major W tiles (544B; conflict-free LDS.64)
__global__ __launch_bounds__(512, 1) void k_group(float* __restrict__ outFeat){
  extern __shared__ float sm[];
  float* H   = sm;                     // [128][LDW]
  float* W2s = sm + 128*LDW;           // frag-major, 128*136 floats
  float* W3s = W2s + 128*136;
  __shared__ int   sIdx[NS];
  __shared__ float sCtr[3];
  __shared__ float sWx[3*128];
  __shared__ float sB1[128], sB2[128];
  __shared__ float psm[8*128];

  int bk = blockIdx.y, p = blockIdx.x, t = threadIdx.x;
  int w = t >> 5, lane = t & 31;
  int gid = lane >> 2, tq = lane & 3;
  int mw = w & 7, ng = w >> 3;
  int m0 = mw*16, n0 = ng*64;

  int gp_ = bk*NP + p;
  if (t < NS) sIdx[t] = g_gidx[gp_*NS + t];
  if (t < 3)  sCtr[t] = g_newxyz[gp_*3 + t];
  if (t < 384) sWx[t] = g_W1x[t];
  if (t < 128){ sB1[t]=g_bM1[t]; sB2[t]=g_bM2[t]; }
  // weight copies (linear, coalesced): 4352 uint4 each
  for (int i = t; i < 4352; i += 512){
    ((uint4*)W2s)[i] = ((const uint4*)g_W2F)[i];
    ((uint4*)W3s)[i] = ((const uint4*)g_W3F)[i];
  }
  // ---- layer 1 build: H[s][c] tf32-rounded ----
  {
    int s = t >> 2, ob = (t & 3)*32;
    int m = sIdx[s];   // note: sIdx written by t<128 this block; need sync first
    // (sync below before use)
    __syncthreads();
    m = sIdx[s];
    const float* xp = g_x + (bk*MM + m)*3;
    float gx = __fdiv_rn(__fsub_rn(xp[0], sCtr[0]), 0.15f);
    float gy = __fdiv_rn(__fsub_rn(xp[1], sCtr[1]), 0.15f);
    float gz = __fdiv_rn(__fsub_rn(xp[2], sCtr[2]), 0.15f);
    const float4* fp = (const float4*)(g_F1 + ((size_t)bk*MM + m)*128 + ob);
#pragma unroll
    for (int j4 = 0; j4 < 8; j4++){
      float4 fv = fp[j4];
      int o = ob + j4*4;
      float4 u;
      u.x = tf32r(fmaxf(fv.x + sWx[o]*gx   + sWx[128+o]*gy   + sWx[256+o]*gz   + sB1[o],   0.f));
      u.y = tf32r(fmaxf(fv.y + sWx[o+1]*gx + sWx[128+o+1]*gy + sWx[256+o+1]*gz + sB1[o+1], 0.f));
      u.z = tf32r(fmaxf(fv.z + sWx[o+2]*gx + sWx[128+o+2]*gy + sWx[256+o+2]*gz + sB1[o+2], 0.f));
      u.w = tf32r(fmaxf(fv.w + sWx[o+3]*gx + sWx[128+o+3]*gy + sWx[256+o+3]*gz + sB1[o+3], 0.f));
      *(float4*)(H + s*LDW + o) = u;
    }
  }
  __syncthreads();

  const u32* Hu  = (const u32*)H;
  const u64* W2u = (const u64*)W2s;
  const u64* W3u = (const u64*)W3s;
  float acc[8][4];

  // ---- GEMM 1: D1 = H * W2^T ----
#pragma unroll
  for (int nt=0;nt<8;nt++)
#pragma unroll
    for (int j=0;j<4;j++) acc[nt][j] = 0.f;
#pragma unroll
  for (int ks = 0; ks < 16; ks++){
    int kc = ks*8;
    u32 a[4];
    a[0] = Hu[(m0+gid)*LDW + kc + tq];
    a[1] = Hu[(m0+8+gid)*LDW + kc + tq];
    a[2] = Hu[(m0+gid)*LDW + kc + tq + 4];
    a[3] = Hu[(m0+8+gid)*LDW + kc + tq + 4];
    u64 bw[8];
#pragma unroll
    for (int nt = 0; nt < 8; nt++)
      bw[nt] = W2u[(n0 + nt*8 + gid)*WST + ks*4 + tq];
#pragma unroll
    for (int nt = 0; nt < 8; nt++){
      u32 b2[2] = { (u32)bw[nt], (u32)(bw[nt] >> 32) };
      mma_tf32(acc[nt], a, b2);
    }
  }
  __syncthreads();

  // ---- epilogue: H' = tf32(relu(D1 + b2)) ----
  {
    int r0 = m0 + gid;
#pragma unroll
    for (int nt = 0; nt < 8; nt++){
      int c0 = n0 + nt*8 + 2*tq;
      float b0v = sB2[c0], b1v = sB2[c0+1];
      float2 v;
      v.x = tf32r(fmaxf(acc[nt][0] + b0v, 0.f));
      v.y = tf32r(fmaxf(acc[nt][1] + b1v, 0.f));
      *(float2*)(H + r0*LDW + c0) = v;
      v.x = tf32r(fmaxf(acc[nt][2] + b0v, 0.f));
      v.y = tf32r(fmaxf(acc[nt][3] + b1v, 0.f));
      *(float2*)(H + (r0+8)*LDW + c0) = v;
    }
  }
  __syncthreads();

  // ---- GEMM 2: D2 = H' * W3^T ----
#pragma unroll
  for (int nt=0;nt<8;nt++)
#pragma unroll
    for (int j=0;j<4;j++) acc[nt][j] = 0.f;
#pragma unroll
  for (int ks = 0; ks < 16; ks++){
    int kc = ks*8;
    u32 a[4];
    a[0] = Hu[(m0+gid)*LDW + kc + tq];
    a[1] = Hu[(m0+8+gid)*LDW + kc + tq];
    a[2] = Hu[(m0+gid)*LDW + kc + tq + 4];
    a[3] = Hu[(m0+8+gid)*LDW + kc + tq + 4];
    u64 bw[8];
#pragma unroll
    for (int nt = 0; nt < 8; nt++)
      bw[nt] = W3u[(n0 + nt*8 + gid)*WST + ks*4 + tq];
#pragma unroll
    for (int nt = 0; nt < 8; nt++){
      u32 b2[2] = { (u32)bw[nt], (u32)(bw[nt] >> 32) };
      mma_tf32(acc[nt], a, b2);
    }
  }

  // ---- maxpool over s ----
  float cm0[8], cm1[8];
#pragma unroll
  for (int nt = 0; nt < 8; nt++){
    cm0[nt] = fmaxf(acc[nt][0], acc[nt][2]);
    cm1[nt] = fmaxf(acc[nt][1], acc[nt][3]);
  }
#pragma unroll
  for (int off = 4; off < 32; off <<= 1){
#pragma unroll
    for (int nt = 0; nt < 8; nt++){
      cm0[nt] = fmaxf(cm0[nt], __shfl_xor_sync(0xffffffffu, cm0[nt], off));
      cm1[nt] = fmaxf(cm1[nt], __shfl_xor_sync(0xffffffffu, cm1[nt], off));
    }
  }
  if (gid == 0){
#pragma unroll
    for (int nt = 0; nt < 8; nt++){
      psm[mw*128 + n0 + nt*8 + 2*tq]     = cm0[nt];
      psm[mw*128 + n0 + nt*8 + 2*tq + 1] = cm1[nt];
    }
  }
  __syncthreads();
  if (t < 128){
    float mx = psm[t];
#pragma unroll
    for (int r = 1; r < 8; r++) mx = fmaxf(mx, psm[r*128 + t]);
    float res = fmaxf(mx + g_bM3[t], 0.f);
    int fo = (bk*128 + t)*NP + p;
    g_feat[fo] = res;
    outFeat[fo] = res;
  }
}

// ---------------- launch 4: c1 + c2 + head ----------------
__global__ __launch_bounds__(256) void k_c12h(const float* __restrict__ opw,
                                              const float* __restrict__ opb,
                                              float* __restrict__ outScores){
  extern __shared__ float sm[];
  float* sH = sm;
  float* sW = sm + 16384;
  __shared__ float sOp[5*128]; __shared__ float sOb[5];
  int bk = blockIdx.x, t = threadIdx.x;
  int k = bk % KK;
  for (int i = t; i < 640; i += 256) sOp[i] = opw[k*640 + i];
  if (t < 5) sOb[t] = opb[k*5 + t];
#pragma unroll
  for (int r = 0; r < 16; r++){
    ((float4*)sH)[r*256 + t] = ((const float4*)(g_feat + bk*16384))[r*256 + t];
    ((float4*)sW)[r*256 + t] = ((const float4*)g_C1T)[r*256 + t];
  }
  __syncthreads();
  int s0 = (t & 15)*8, o0 = (t >> 4)*8;
  u64 acc[8][4]; zacc8(acc);
  gemm8x8<128>(sH, sW, acc, s0, o0);
  float2 bb[4];
#pragma unroll
  for (int j = 0; j < 4; j++) bb[j] = *(const float2*)(g_bC1 + o0 + 2*j);
  __syncthreads();
#pragma unroll
  for (int si = 0; si < 8; si++)
#pragma unroll
    for (int j = 0; j < 4; j++){
      float2 v = upk(acc[si][j]);
      sH[(o0+2*j)*128 + s0+si]   = fmaxf(v.x + bb[j].x, 0.f);
      sH[(o0+2*j+1)*128 + s0+si] = fmaxf(v.y + bb[j].y, 0.f);
    }
#pragma unroll
  for (int r = 0; r < 16; r++) ((float4*)sW)[r*256 + t] = ((const float4*)g_C2T)[r*256 + t];
  __syncthreads();
  zacc8(acc);
  gemm8x8<128>(sH, sW, acc, s0, o0);
#pragma unroll
  for (int j = 0; j < 4; j++) bb[j] = *(const float2*)(g_bC2 + o0 + 2*j);
  __syncthreads();
#pragma unroll
  for (int si = 0; si < 8; si++)
#pragma unroll
    for (int j = 0; j < 4; j++){
      float2 v = upk(acc[si][j]);
      sH[(o0+2*j)*128 + s0+si]   = fmaxf(v.x + bb[j].x, 0.f);
      sH[(o0+2*j+1)*128 + s0+si] = fmaxf(v.y + bb[j].y, 0.f);
    }
  __syncthreads();
  if (t < 128){
    float a0=0,a1=0,a2=0,a3=0,a4=0;
#pragma unroll 4
    for (int c = 0; c < 128; c++){
      float nv = sH[c*128 + t];
      a0 += sOp[c]*nv; a1 += sOp[128+c]*nv; a2 += sOp[256+c]*nv; a3 += sOp[384+c]*nv; a4 += sOp[512+c]*nv;
    }
    a0+=sOb[0]; a1+=sOb[1]; a2+=sOb[2]; a3+=sOb[3]; a4+=sOb[4];
    const float* nz = g_newxyz + (bk*NP + t)*3;
    float* o = outScores + (bk*NP + t)*5;
    o[0]=a0; o[1]=a1; o[2]=nz[0]+a2; o[3]=nz[1]+a3; o[4]=nz[2]+a4;
  }
}

// ---------------- launcher ----------------
extern "C" void kernel_launch(void* const* d_in, const int* in_sizes, int n_in,
                              void* d_out, int out_size){
  (void)in_sizes; (void)n_in; (void)out_size;
  const float* xyz  = (const float*)d_in[0];
  const float* feats= (const float*)d_in[1];
  const float* m1_w = (const float*)d_in[2];
  const float* m1_b = (const float*)d_in[3];
  const float* m1_g = (const float*)d_in[4];
  const float* m1_be= (const float*)d_in[5];
  const float* m2_w = (const float*)d_in[6];
  const float* m2_b = (const float*)d_in[7];
  const float* m2_g = (const float*)d_in[8];
  const float* m2_be= (const float*)d_in[9];
  const float* m3_w = (const float*)d_in[10];
  const float* m3_b = (const float*)d_in[11];
  const float* m3_g = (const float*)d_in[12];
  const float* m3_be= (const float*)d_in[13];
  const float* c1_w = (const float*)d_in[14];
  const float* c1_b = (const float*)d_in[15];
  const float* c1_g = (const float*)d_in[16];
  const float* c1_be= (const float*)d_in[17];
  const float* c2_w = (const float*)d_in[18];
  const float* c2_b = (const float*)d_in[19];
  const float* c2_g = (const float*)d_in[20];
  const float* c2_be= (const float*)d_in[21];
  const float* op_w = (const float*)d_in[22];
  const float* op_b = (const float*)d_in[23];

  float* out = (float*)d_out;
  float* outScores = out;                 // 38*128*5
  float* outAgg    = out + 24320;         // 38*128*3
  float* outFeat   = out + 38912;         // 38*128*128

  const int GRP_SMEM = (128*LDW + 2*128*136)*4;   // 67584 + 139264 = 206848
  cudaFuncSetAttribute(k_ball_f1, cudaFuncAttributeMaxDynamicSharedMemorySize, 65536);
  cudaFuncSetAttribute(k_group,   cudaFuncAttributeMaxDynamicSharedMemorySize, GRP_SMEM);
  cudaFuncSetAttribute(k_c12h,    cudaFuncAttributeMaxDynamicSharedMemorySize, 131072);

  k_prep_fold<<<844, 256>>>(xyz, m1_w, m1_g, m2_w, m2_g,               // 0
      m3_w, m3_g, c1_w, c1_g, c2_w, c2_g,
      m1_b, m1_be, m2_b, m2_be, m3_b, m3_be, c1_b, c1_be, c2_b, c2_be);
  k_fps<<<BKT, 1024>>>(outAgg);                                        // 1
  k_ball_f1<<<608 + BKT*8, 256, 65536>>>(feats);                       // 2
  k_group<<<dim3(NP, BKT), 512, GRP_SMEM>>>(outFeat);                  // 3 <- profiled
  k_c12h<<<BKT, 256, 131072>>>(op_w, op_b, outScores);                 // 4
}

// round 13
// speedup vs baseline: 2.0448x; 1.7862x over previous
#include <cuda_runtime.h>
#include <cuda_fp16.h>
#include <stdint.h>

typedef unsigned long long u64;
typedef uint32_t u32;

#define BB 2
#define KK 19
#define BKT 38
#define MM 1024
#define CC 256
#define NP 128
#define NS 128

// ---------------- device scratch ----------------
__device__ float g_x[BKT*MM*3];
__device__ float g_F1[BKT*MM*128];
__device__ float g_newxyz[BKT*NP*3];
__device__ int   g_gidx[BKT*NP*NS];
__device__ float g_feat[BKT*128*NP];
__device__ float g_W1T[CC*128];      // [c][o] fp32 (FFMA2 k_f1)
__device__ u32   g_W2H[128*68];      // [o][kk] half2 pairs along k, stride 68
__device__ u32   g_W3H[128*68];
__device__ float g_C1T[128*128];     // [c][o] fp32
__device__ float g_C2T[128*128];
__device__ float g_W1x[3*128];
__device__ float g_bM1[128], g_bM2[128], g_bM3[128], g_bC1[128], g_bC2[128];

// ---------------- fp16 helpers ----------------
__device__ __forceinline__ u32 h2pk(float a, float b){
  __half2 h = __floats2half2_rn(a, b);
  return *(u32*)&h;
}
__device__ __forceinline__ void mma_f16(float d[4], const u32 a[4], const u32 b[2]){
  asm volatile("mma.sync.aligned.m16n8k16.row.col.f32.f16.f16.f32 "
    "{%0,%1,%2,%3}, {%4,%5,%6,%7}, {%8,%9}, {%0,%1,%2,%3};"
    : "+f"(d[0]), "+f"(d[1]), "+f"(d[2]), "+f"(d[3])
    : "r"(a[0]), "r"(a[1]), "r"(a[2]), "r"(a[3]), "r"(b[0]), "r"(b[1]));
}

// ---------------- f32x2 helpers ----------------
__device__ __forceinline__ u64 pk2(float a){ u64 r; asm("mov.b64 %0, {%1, %1};" : "=l"(r) : "f"(a)); return r; }
__device__ __forceinline__ void fma2(u64& d, u64 a, u64 b){ asm("fma.rn.f32x2 %0, %1, %2, %0;" : "+l"(d) : "l"(a), "l"(b)); }
__device__ __forceinline__ float2 upk(u64 v){ float2 r; asm("mov.b64 {%0, %1}, %2;" : "=f"(r.x), "=f"(r.y) : "l"(v)); return r; }
__device__ __forceinline__ void zacc8(u64 acc[8][4]){
#pragma unroll
  for (int i=0;i<8;i++)
#pragma unroll
    for (int j=0;j<4;j++) acc[i][j]=0ull;
}
#define GROW(i, av) { u64 a_=pk2(av); fma2(acc[i][0],a_,b0); fma2(acc[i][1],a_,b1); fma2(acc[i][2],a_,b2); fma2(acc[i][3],a_,b3); }
template<int KC>
__device__ __forceinline__ void gemm8x8(const float* sA, const float* sB, u64 acc[8][4], int s0, int o0){
#pragma unroll 4
  for (int c = 0; c < KC; c++){
    float4 a0 = *(const float4*)(sA + c*128 + s0);
    float4 a1 = *(const float4*)(sA + c*128 + s0 + 4);
    const u64* bp = (const u64*)(sB + c*128 + o0);
    u64 b0=bp[0], b1=bp[1], b2=bp[2], b3=bp[3];
    GROW(0,a0.x) GROW(1,a0.y) GROW(2,a0.z) GROW(3,a0.w)
    GROW(4,a1.x) GROW(5,a1.y) GROW(6,a1.z) GROW(7,a1.w)
  }
}

__device__ __forceinline__ float d2f(float ax,float ay,float az,float bx,float by,float bz){
  float dx=__fsub_rn(ax,bx), dy=__fsub_rn(ay,by), dz=__fsub_rn(az,bz);
  return __fadd_rn(__fadd_rn(__fmul_rn(dx,dx),__fmul_rn(dy,dy)),__fmul_rn(dz,dz));
}
__device__ __forceinline__ float gpv(float g){ return __fdiv_rn(g, sqrtf(1.0f + 1e-5f)); }

// ---------------- launch 0: prep x + fold everything ----------------
// prep_x 116736 | W1T 32768 | W2H 8704 | W3H 8704 | C1T 16384 | C2T 16384 | bias 640 | W1x 384 = 200704
__global__ void k_prep_fold(const float* __restrict__ xyz,
                            const float* m1w, const float* m1g,
                            const float* m2w, const float* m2g,
                            const float* m3w, const float* m3g,
                            const float* c1w, const float* c1g,
                            const float* c2w, const float* c2g,
                            const float* m1b, const float* m1be,
                            const float* m2b, const float* m2be,
                            const float* m3b, const float* m3be,
                            const float* c1b, const float* c1be,
                            const float* c2b, const float* c2be){
  int i = blockIdx.x*256 + threadIdx.x;
  if (i < 116736){
    int j = i % 3, rest = i / 3;
    int m = rest % MM, bk = rest / MM;
    int b = bk / KK, k = bk % KK;
    g_x[i] = xyz[((size_t)(b*MM + m)*KK + k)*3 + j];
    return;
  } i -= 116736;
  if (i < 32768){                 // W1T [c][o]
    int c = i>>7, o = i&127;
    g_W1T[i] = m1w[o*259 + 3 + c] * gpv(m1g[o]);
    return;
  } i -= 32768;
  if (i < 8704){                  // W2H half2 pairs
    int o = i/68, kk = i%68;
    u32 v = 0;
    if (kk < 64){
      float gp = gpv(m2g[o]);
      v = h2pk(m2w[o*128 + 2*kk]*gp, m2w[o*128 + 2*kk + 1]*gp);
    }
    g_W2H[i] = v;
    return;
  } i -= 8704;
  if (i < 8704){
    int o = i/68, kk = i%68;
    u32 v = 0;
    if (kk < 64){
      float gp = gpv(m3g[o]);
      v = h2pk(m3w[o*128 + 2*kk]*gp, m3w[o*128 + 2*kk + 1]*gp);
    }
    g_W3H[i] = v;
    return;
  } i -= 8704;
  if (i < 16384){                 // C1T [c][o]
    int c = i>>7, o = i&127;
    g_C1T[i] = c1w[o*128+c] * gpv(c1g[o]);
    return;
  } i -= 16384;
  if (i < 16384){
    int c = i>>7, o = i&127;
    g_C2T[i] = c2w[o*128+c] * gpv(c2g[o]);
    return;
  } i -= 16384;
  if (i < 640){
    int which = i>>7, o = i&127;
    const float* b  = which==0?m1b: which==1?m2b: which==2?m3b: which==3?c1b:c2b;
    const float* g  = which==0?m1g: which==1?m2g: which==2?m3g: which==3?c1g:c2g;
    const float* be = which==0?m1be:which==1?m2be:which==2?m3be:which==3?c1be:c2be;
    float* dst = which==0?g_bM1: which==1?g_bM2: which==2?g_bM3: which==3?g_bC1:g_bC2;
    dst[o] = b[o]*gpv(g[o]) + be[o];
    return;
  } i -= 640;
  if (i < 384){
    int j = i>>7, o = i&127;
    g_W1x[i] = m1w[o*259 + j] * gpv(m1g[o]);
  }
}

// ---------------- launch 1: FPS ----------------
__global__ __launch_bounds__(1024) void k_fps(float* __restrict__ outAgg){
  int bk = blockIdx.x, t = threadIdx.x;
  const float* xb = g_x + bk*MM*3;
  float px = xb[t*3], py = xb[t*3+1], pz = xb[t*3+2];
  float dist = 1e10f;
  __shared__ float sc[3]; __shared__ float sv[32]; __shared__ int sw_[32]; __shared__ int sfar;
  if (t == 0) sfar = 0;
  __syncthreads();
  int lane = t & 31, wp = t >> 5;
  for (int i = 0; i < NP; i++){
    if (t == 0){
      int f = sfar;
      float cx = xb[f*3], cy = xb[f*3+1], cz = xb[f*3+2];
      sc[0]=cx; sc[1]=cy; sc[2]=cz;
      float* nz = g_newxyz + (bk*NP+i)*3; nz[0]=cx; nz[1]=cy; nz[2]=cz;
      float* oa = outAgg + (bk*NP+i)*3;   oa[0]=cx; oa[1]=cy; oa[2]=cz;
    }
    __syncthreads();
    float d = d2f(px,py,pz, sc[0],sc[1],sc[2]);
    dist = fminf(dist, d);
    float v = dist; int ix = t;
#pragma unroll
    for (int off=16; off; off>>=1){
      float ov = __shfl_down_sync(0xffffffffu, v, off);
      int   oi = __shfl_down_sync(0xffffffffu, ix, off);
      if (ov > v || (ov == v && oi < ix)){ v = ov; ix = oi; }
    }
    if (lane == 0){ sv[wp] = v; sw_[wp] = ix; }
    __syncthreads();
    if (t < 32){
      v = sv[t]; ix = sw_[t];
#pragma unroll
      for (int off=16; off; off>>=1){
        float ov = __shfl_down_sync(0xffffffffu, v, off);
        int   oi = __shfl_down_sync(0xffffffffu, ix, off);
        if (ov > v || (ov == v && oi < ix)){ v = ov; ix = oi; }
      }
      if (t == 0) sfar = ix;
    }
    __syncthreads();
  }
}

// ---------------- launch 2: fused ball (blocks 0..607) + F1 (blocks 608..911) ----
__device__ void ball_body(){
  int w = blockIdx.x*8 + (threadIdx.x >> 5);
  int lane = threadIdx.x & 31;
  int bk = w / NP;
  const float* ctr = g_newxyz + w*3;
  float cx=ctr[0], cy=ctr[1], cz=ctr[2];
  const float R2 = (float)(0.15*0.15);
  int base = w*NS;
  int cnt = 0, first = 0;
  for (int ch = 0; ch < MM/32; ch++){
    int m = ch*32 + lane;
    const float* xp = g_x + (bk*MM + m)*3;
    float d = d2f(cx,cy,cz, xp[0],xp[1],xp[2]);
    unsigned mask = __ballot_sync(0xffffffffu, d < R2);
    if (cnt == 0 && mask) first = ch*32 + __ffs(mask) - 1;
    int pos = cnt + __popc(mask & ((1u<<lane)-1u));
    if ((d < R2) && pos < NS) g_gidx[base + pos] = m;
    cnt += __popc(mask);
    if (cnt >= NS) break;
  }
  for (int j = cnt + lane; j < NS; j += 32) g_gidx[base + j] = first;
}

__device__ void f1_body(const float* __restrict__ features, float* sm){
  float* sF = sm;
  float* sW = sm + 64*128;
  int fb = blockIdx.x - 608;
  int bk = fb >> 3, mb = (fb & 7)*128;
  int b = bk / KK, k = bk % KK;
  int t = threadIdx.x;
  int s0 = (t & 15)*8, o0 = (t >> 4)*8;
  u64 acc[8][4]; zacc8(acc);
  for (int c0 = 0; c0 < CC; c0 += 64){
#pragma unroll
    for (int r = 0; r < 8; r++){
      int e4 = r*256 + t;
      int ci = e4 >> 5, mi4 = e4 & 31;
      ((float4*)sF)[e4] = *(const float4*)(features + ((size_t)(b*CC + c0 + ci)*KK + k)*MM + mb + mi4*4);
    }
#pragma unroll
    for (int r = 0; r < 8; r++){
      int e4 = r*256 + t;
      ((float4*)sW)[e4] = ((const float4*)(g_W1T + c0*128))[e4];
    }
    __syncthreads();
    gemm8x8<64>(sF, sW, acc, s0, o0);
    __syncthreads();
  }
#pragma unroll
  for (int si = 0; si < 8; si++){
    size_t row = (size_t)bk*MM + mb + s0 + si;
#pragma unroll
    for (int j = 0; j < 4; j++)
      *(float2*)(g_F1 + row*128 + o0 + 2*j) = upk(acc[si][j]);
  }
}

__global__ __launch_bounds__(256) void k_ball_f1(const float* __restrict__ features){
  extern __shared__ float smdyn[];
  if (blockIdx.x < 608) ball_body();
  else                  f1_body(features, smdyn);
}

// ---------------- launch 3 (PROFILED): group, fp16 HMMA, 256 thr, 2 CTA/SM ----------------
// smem: Hu[128*68] | W2u[128*68] | W3u[128*68] u32 = 104448 B
__global__ __launch_bounds__(256, 2) void k_group(float* __restrict__ outFeat){
  extern __shared__ u32 smu[];
  u32* Hu  = smu;
  u32* W2u = smu + 128*68;
  u32* W3u = smu + 2*128*68;
  __shared__ int   sIdx[NS];
  __shared__ float sCtr[3];
  __shared__ float sWx[3*128];
  __shared__ float sB1[128], sB2[128];

  int bk = blockIdx.y, p = blockIdx.x, t = threadIdx.x;
  int w = t >> 5, lane = t & 31;
  int gid = lane >> 2, tig = lane & 3;
  int m0 = (w & 3)*32, n0 = (w >> 2)*64;

  int gp_ = bk*NP + p;
  if (t < NS) sIdx[t] = g_gidx[gp_*NS + t];
  if (t < 3)  sCtr[t] = g_newxyz[gp_*3 + t];
  if (t < 128){ sB1[t]=g_bM1[t]; sB2[t]=g_bM2[t]; }
  for (int i = t; i < 384; i += 256) sWx[i] = g_W1x[i];
  // weight copies: 2176 uint4 each
  for (int i = t; i < 2176; i += 256){
    ((uint4*)W2u)[i] = ((const uint4*)g_W2H)[i];
    ((uint4*)W3u)[i] = ((const uint4*)g_W3H)[i];
  }
  __syncthreads();

  // ---- layer 1 build: H[s][c] as half2 ----
  {
    int s = t >> 1, ob = (t & 1)*64;
    int m = sIdx[s];
    const float* xp = g_x + (bk*MM + m)*3;
    float gx = __fdiv_rn(__fsub_rn(xp[0], sCtr[0]), 0.15f);
    float gy = __fdiv_rn(__fsub_rn(xp[1], sCtr[1]), 0.15f);
    float gz = __fdiv_rn(__fsub_rn(xp[2], sCtr[2]), 0.15f);
    const float4* fp = (const float4*)(g_F1 + ((size_t)bk*MM + m)*128 + ob);
#pragma unroll 4
    for (int j4 = 0; j4 < 16; j4++){
      float4 fv = fp[j4];
      int o = ob + j4*4;
      float v0 = fmaxf(fv.x + sWx[o]*gx   + sWx[128+o]*gy   + sWx[256+o]*gz   + sB1[o],   0.f);
      float v1 = fmaxf(fv.y + sWx[o+1]*gx + sWx[128+o+1]*gy + sWx[256+o+1]*gz + sB1[o+1], 0.f);
      float v2 = fmaxf(fv.z + sWx[o+2]*gx + sWx[128+o+2]*gy + sWx[256+o+2]*gz + sB1[o+2], 0.f);
      float v3 = fmaxf(fv.w + sWx[o+3]*gx + sWx[128+o+3]*gy + sWx[256+o+3]*gz + sB1[o+3], 0.f);
      Hu[s*68 + (o>>1)]     = h2pk(v0, v1);
      Hu[s*68 + (o>>1) + 1] = h2pk(v2, v3);
    }
  }
  __syncthreads();

  float acc[2][8][4];

  // ---- GEMM 1: D1 = H * W2^T ----
#pragma unroll
  for (int mt=0;mt<2;mt++)
#pragma unroll
    for (int nt=0;nt<8;nt++)
#pragma unroll
      for (int j=0;j<4;j++) acc[mt][nt][j] = 0.f;
#pragma unroll
  for (int ks = 0; ks < 8; ks++){
    int kk = ks*8;
    u32 a[2][4];
#pragma unroll
    for (int mt = 0; mt < 2; mt++){
      int r = m0 + mt*16 + gid;
      a[mt][0] = Hu[r*68 + kk + tig];
      a[mt][1] = Hu[(r+8)*68 + kk + tig];
      a[mt][2] = Hu[r*68 + kk + 4 + tig];
      a[mt][3] = Hu[(r+8)*68 + kk + 4 + tig];
    }
#pragma unroll
    for (int nt = 0; nt < 8; nt++){
      u32 b[2];
      b[0] = W2u[(n0 + nt*8 + gid)*68 + kk + tig];
      b[1] = W2u[(n0 + nt*8 + gid)*68 + kk + 4 + tig];
      mma_f16(acc[0][nt], a[0], b);
      mma_f16(acc[1][nt], a[1], b);
    }
  }
  __syncthreads();

  // ---- epilogue: H' = fp16(relu(D1 + b2)) ----
#pragma unroll
  for (int mt = 0; mt < 2; mt++){
    int r0 = m0 + mt*16 + gid;
#pragma unroll
    for (int nt = 0; nt < 8; nt++){
      int c0 = n0 + nt*8 + 2*tig;
      int ch = (c0 >> 1);
      float b0v = sB2[c0], b1v = sB2[c0+1];
      Hu[r0*68 + ch]     = h2pk(fmaxf(acc[mt][nt][0] + b0v, 0.f), fmaxf(acc[mt][nt][1] + b1v, 0.f));
      Hu[(r0+8)*68 + ch] = h2pk(fmaxf(acc[mt][nt][2] + b0v, 0.f), fmaxf(acc[mt][nt][3] + b1v, 0.f));
    }
  }
  __syncthreads();

  // ---- GEMM 2: D2 = H' * W3^T ----
#pragma unroll
  for (int mt=0;mt<2;mt++)
#pragma unroll
    for (int nt=0;nt<8;nt++)
#pragma unroll
      for (int j=0;j<4;j++) acc[mt][nt][j] = 0.f;
#pragma unroll
  for (int ks = 0; ks < 8; ks++){
    int kk = ks*8;
    u32 a[2][4];
#pragma unroll
    for (int mt = 0; mt < 2; mt++){
      int r = m0 + mt*16 + gid;
      a[mt][0] = Hu[r*68 + kk + tig];
      a[mt][1] = Hu[(r+8)*68 + kk + tig];
      a[mt][2] = Hu[r*68 + kk + 4 + tig];
      a[mt][3] = Hu[(r+8)*68 + kk + 4 + tig];
    }
#pragma unroll
    for (int nt = 0; nt < 8; nt++){
      u32 b[2];
      b[0] = W3u[(n0 + nt*8 + gid)*68 + kk + tig];
      b[1] = W3u[(n0 + nt*8 + gid)*68 + kk + 4 + tig];
      mma_f16(acc[0][nt], a[0], b);
      mma_f16(acc[1][nt], a[1], b);
    }
  }

  // ---- maxpool over s ----
  float cm0[8], cm1[8];
#pragma unroll
  for (int nt = 0; nt < 8; nt++){
    cm0[nt] = fmaxf(fmaxf(acc[0][nt][0], acc[0][nt][2]), fmaxf(acc[1][nt][0], acc[1][nt][2]));
    cm1[nt] = fmaxf(fmaxf(acc[0][nt][1], acc[0][nt][3]), fmaxf(acc[1][nt][1], acc[1][nt][3]));
  }
#pragma unroll
  for (int off = 4; off < 32; off <<= 1){
#pragma unroll
    for (int nt = 0; nt < 8; nt++){
      cm0[nt] = fmaxf(cm0[nt], __shfl_xor_sync(0xffffffffu, cm0[nt], off));
      cm1[nt] = fmaxf(cm1[nt], __shfl_xor_sync(0xffffffffu, cm1[nt], off));
    }
  }
  __syncthreads();               // GEMM2 done everywhere; W2u reusable
  float* psm = (float*)W2u;      // [4][128]
  if (gid == 0){
#pragma unroll
    for (int nt = 0; nt < 8; nt++){
      psm[(w & 3)*128 + n0 + nt*8 + 2*tig]     = cm0[nt];
      psm[(w & 3)*128 + n0 + nt*8 + 2*tig + 1] = cm1[nt];
    }
  }
  __syncthreads();
  if (t < 128){
    float mx = fmaxf(fmaxf(psm[t], psm[128+t]), fmaxf(psm[256+t], psm[384+t]));
    float res = fmaxf(mx + g_bM3[t], 0.f);
    int fo = (bk*128 + t)*NP + p;
    g_feat[fo] = res;
    outFeat[fo] = res;
  }
}

// ---------------- launch 4: c1 + c2 + head ----------------
__global__ __launch_bounds__(256) void k_c12h(const float* __restrict__ opw,
                                              const float* __restrict__ opb,
                                              float* __restrict__ outScores){
  extern __shared__ float sm[];
  float* sH = sm;
  float* sW = sm + 16384;
  __shared__ float sOp[5*128]; __shared__ float sOb[5];
  int bk = blockIdx.x, t = threadIdx.x;
  int k = bk % KK;
  for (int i = t; i < 640; i += 256) sOp[i] = opw[k*640 + i];
  if (t < 5) sOb[t] = opb[k*5 + t];
#pragma unroll
  for (int r = 0; r < 16; r++){
    ((float4*)sH)[r*256 + t] = ((const float4*)(g_feat + bk*16384))[r*256 + t];
    ((float4*)sW)[r*256 + t] = ((const float4*)g_C1T)[r*256 + t];
  }
  __syncthreads();
  int s0 = (t & 15)*8, o0 = (t >> 4)*8;
  u64 acc[8][4]; zacc8(acc);
  gemm8x8<128>(sH, sW, acc, s0, o0);
  float2 bb[4];
#pragma unroll
  for (int j = 0; j < 4; j++) bb[j] = *(const float2*)(g_bC1 + o0 + 2*j);
  __syncthreads();
#pragma unroll
  for (int si = 0; si < 8; si++)
#pragma unroll
    for (int j = 0; j < 4; j++){
      float2 v = upk(acc[si][j]);
      sH[(o0+2*j)*128 + s0+si]   = fmaxf(v.x + bb[j].x, 0.f);
      sH[(o0+2*j+1)*128 + s0+si] = fmaxf(v.y + bb[j].y, 0.f);
    }
#pragma unroll
  for (int r = 0; r < 16; r++) ((float4*)sW)[r*256 + t] = ((const float4*)g_C2T)[r*256 + t];
  __syncthreads();
  zacc8(acc);
  gemm8x8<128>(sH, sW, acc, s0, o0);
#pragma unroll
  for (int j = 0; j < 4; j++) bb[j] = *(const float2*)(g_bC2 + o0 + 2*j);
  __syncthreads();
#pragma unroll
  for (int si = 0; si < 8; si++)
#pragma unroll
    for (int j = 0; j < 4; j++){
      float2 v = upk(acc[si][j]);
      sH[(o0+2*j)*128 + s0+si]   = fmaxf(v.x + bb[j].x, 0.f);
      sH[(o0+2*j+1)*128 + s0+si] = fmaxf(v.y + bb[j].y, 0.f);
    }
  __syncthreads();
  if (t < 128){
    float a0=0,a1=0,a2=0,a3=0,a4=0;
#pragma unroll 4
    for (int c = 0; c < 128; c++){
      float nv = sH[c*128 + t];
      a0 += sOp[c]*nv; a1 += sOp[128+c]*nv; a2 += sOp[256+c]*nv; a3 += sOp[384+c]*nv; a4 += sOp[512+c]*nv;
    }
    a0+=sOb[0]; a1+=sOb[1]; a2+=sOb[2]; a3+=sOb[3]; a4+=sOb[4];
    const float* nz = g_newxyz + (bk*NP + t)*3;
    float* o = outScores + (bk*NP + t)*5;
    o[0]=a0; o[1]=a1; o[2]=nz[0]+a2; o[3]=nz[1]+a3; o[4]=nz[2]+a4;
  }
}

// ---------------- launcher ----------------
extern "C" void kernel_launch(void* const* d_in, const int* in_sizes, int n_in,
                              void* d_out, int out_size){
  (void)in_sizes; (void)n_in; (void)out_size;
  const float* xyz  = (const float*)d_in[0];
  const float* feats= (const float*)d_in[1];
  const float* m1_w = (const float*)d_in[2];
  const float* m1_b = (const float*)d_in[3];
  const float* m1_g = (const float*)d_in[4];
  const float* m1_be= (const float*)d_in[5];
  const float* m2_w = (const float*)d_in[6];
  const float* m2_b = (const float*)d_in[7];
  const float* m2_g = (const float*)d_in[8];
  const float* m2_be= (const float*)d_in[9];
  const float* m3_w = (const float*)d_in[10];
  const float* m3_b = (const float*)d_in[11];
  const float* m3_g = (const float*)d_in[12];
  const float* m3_be= (const float*)d_in[13];
  const float* c1_w = (const float*)d_in[14];
  const float* c1_b = (const float*)d_in[15];
  const float* c1_g = (const float*)d_in[16];
  const float* c1_be= (const float*)d_in[17];
  const float* c2_w = (const float*)d_in[18];
  const float* c2_b = (const float*)d_in[19];
  const float* c2_g = (const float*)d_in[20];
  const float* c2_be= (const float*)d_in[21];
  const float* op_w = (const float*)d_in[22];
  const float* op_b = (const float*)d_in[23];

  float* out = (float*)d_out;
  float* outScores = out;                 // 38*128*5
  float* outAgg    = out + 24320;         // 38*128*3
  float* outFeat   = out + 38912;         // 38*128*128

  const int GRP_SMEM = 3*128*68*4;        // 104448
  cudaFuncSetAttribute(k_ball_f1, cudaFuncAttributeMaxDynamicSharedMemorySize, 65536);
  cudaFuncSetAttribute(k_group,   cudaFuncAttributeMaxDynamicSharedMemorySize, GRP_SMEM);
  cudaFuncSetAttribute(k_c12h,    cudaFuncAttributeMaxDynamicSharedMemorySize, 131072);

  k_prep_fold<<<784, 256>>>(xyz, m1_w, m1_g, m2_w, m2_g,               // 0
      m3_w, m3_g, c1_w, c1_g, c2_w, c2_g,
      m1_b, m1_be, m2_b, m2_be, m3_b, m3_be, c1_b, c1_be, c2_b, c2_be);
  k_fps<<<BKT, 1024>>>(outAgg);                                        // 1
  k_ball_f1<<<608 + BKT*8, 256, 65536>>>(feats);                       // 2
  k_group<<<dim3(NP, BKT), 256, GRP_SMEM>>>(outFeat);                  // 3 <- profiled
  k_c12h<<<BKT, 256, 131072>>>(op_w, op_b, outScores);                 // 4
}

// round 14
// speedup vs baseline: 2.1277x; 1.0405x over previous
#include <cuda_runtime.h>
#include <cuda_fp16.h>
#include <stdint.h>

typedef unsigned long long u64;
typedef uint32_t u32;

#define BB 2
#define KK 19
#define BKT 38
#define MM 1024
#define CC 256
#define NP 128
#define NS 128
#define NGRP (BKT*NP)   // 4864

// ---------------- device scratch ----------------
__device__ float g_x[BKT*MM*3];
__device__ u32   g_F1H[BKT*MM*64];   // F1 as half2 pairs (o even/odd)
__device__ float g_newxyz[BKT*NP*3];
__device__ int   g_gidx[BKT*NP*NS];
__device__ float g_feat[BKT*128*NP];
__device__ float g_W1T[CC*128];      // [c][o] fp32 (FFMA2 k_f1)
__device__ u32   g_W2H[128*68];      // [o][kk] half2 pairs along k, stride 68
__device__ u32   g_W3H[128*68];
__device__ float g_C1T[128*128];     // [c][o] fp32
__device__ float g_C2T[128*128];
__device__ float g_W1x[3*128];
__device__ float g_bM1[128], g_bM2[128], g_bM3[128], g_bC1[128], g_bC2[128];

// ---------------- fp16 helpers ----------------
__device__ __forceinline__ u32 h2pk(float a, float b){
  __half2 h = __floats2half2_rn(a, b);
  return *(u32*)&h;
}
__device__ __forceinline__ float2 h2up(u32 v){
  return __half22float2(*(__half2*)&v);
}
__device__ __forceinline__ void mma_f16(float d[4], const u32 a[4], const u32 b[2]){
  asm volatile("mma.sync.aligned.m16n8k16.row.col.f32.f16.f16.f32 "
    "{%0,%1,%2,%3}, {%4,%5,%6,%7}, {%8,%9}, {%0,%1,%2,%3};"
    : "+f"(d[0]), "+f"(d[1]), "+f"(d[2]), "+f"(d[3])
    : "r"(a[0]), "r"(a[1]), "r"(a[2]), "r"(a[3]), "r"(b[0]), "r"(b[1]));
}

// ---------------- f32x2 helpers ----------------
__device__ __forceinline__ u64 pk2(float a){ u64 r; asm("mov.b64 %0, {%1, %1};" : "=l"(r) : "f"(a)); return r; }
__device__ __forceinline__ void fma2(u64& d, u64 a, u64 b){ asm("fma.rn.f32x2 %0, %1, %2, %0;" : "+l"(d) : "l"(a), "l"(b)); }
__device__ __forceinline__ float2 upk(u64 v){ float2 r; asm("mov.b64 {%0, %1}, %2;" : "=f"(r.x), "=f"(r.y) : "l"(v)); return r; }
__device__ __forceinline__ void zacc8(u64 acc[8][4]){
#pragma unroll
  for (int i=0;i<8;i++)
#pragma unroll
    for (int j=0;j<4;j++) acc[i][j]=0ull;
}
#define GROW(i, av) { u64 a_=pk2(av); fma2(acc[i][0],a_,b0); fma2(acc[i][1],a_,b1); fma2(acc[i][2],a_,b2); fma2(acc[i][3],a_,b3); }
template<int KC>
__device__ __forceinline__ void gemm8x8(const float* sA, const float* sB, u64 acc[8][4], int s0, int o0){
#pragma unroll 4
  for (int c = 0; c < KC; c++){
    float4 a0 = *(const float4*)(sA + c*128 + s0);
    float4 a1 = *(const float4*)(sA + c*128 + s0 + 4);
    const u64* bp = (const u64*)(sB + c*128 + o0);
    u64 b0=bp[0], b1=bp[1], b2=bp[2], b3=bp[3];
    GROW(0,a0.x) GROW(1,a0.y) GROW(2,a0.z) GROW(3,a0.w)
    GROW(4,a1.x) GROW(5,a1.y) GROW(6,a1.z) GROW(7,a1.w)
  }
}

__device__ __forceinline__ float d2f(float ax,float ay,float az,float bx,float by,float bz){
  float dx=__fsub_rn(ax,bx), dy=__fsub_rn(ay,by), dz=__fsub_rn(az,bz);
  return __fadd_rn(__fadd_rn(__fmul_rn(dx,dx),__fmul_rn(dy,dy)),__fmul_rn(dz,dz));
}
__device__ __forceinline__ float gpv(float g){ return __fdiv_rn(g, sqrtf(1.0f + 1e-5f)); }

// ---------------- launch 0: prep x + fold everything ----------------
__global__ void k_prep_fold(const float* __restrict__ xyz,
                            const float* m1w, const float* m1g,
                            const float* m2w, const float* m2g,
                            const float* m3w, const float* m3g,
                            const float* c1w, const float* c1g,
                            const float* c2w, const float* c2g,
                            const float* m1b, const float* m1be,
                            const float* m2b, const float* m2be,
                            const float* m3b, const float* m3be,
                            const float* c1b, const float* c1be,
                            const float* c2b, const float* c2be){
  int i = blockIdx.x*256 + threadIdx.x;
  if (i < 116736){
    int j = i % 3, rest = i / 3;
    int m = rest % MM, bk = rest / MM;
    int b = bk / KK, k = bk % KK;
    g_x[i] = xyz[((size_t)(b*MM + m)*KK + k)*3 + j];
    return;
  } i -= 116736;
  if (i < 32768){                 // W1T [c][o]
    int c = i>>7, o = i&127;
    g_W1T[i] = m1w[o*259 + 3 + c] * gpv(m1g[o]);
    return;
  } i -= 32768;
  if (i < 8704){                  // W2H half2 pairs
    int o = i/68, kk = i%68;
    u32 v = 0;
    if (kk < 64){
      float gp = gpv(m2g[o]);
      v = h2pk(m2w[o*128 + 2*kk]*gp, m2w[o*128 + 2*kk + 1]*gp);
    }
    g_W2H[i] = v;
    return;
  } i -= 8704;
  if (i < 8704){
    int o = i/68, kk = i%68;
    u32 v = 0;
    if (kk < 64){
      float gp = gpv(m3g[o]);
      v = h2pk(m3w[o*128 + 2*kk]*gp, m3w[o*128 + 2*kk + 1]*gp);
    }
    g_W3H[i] = v;
    return;
  } i -= 8704;
  if (i < 16384){                 // C1T [c][o]
    int c = i>>7, o = i&127;
    g_C1T[i] = c1w[o*128+c] * gpv(c1g[o]);
    return;
  } i -= 16384;
  if (i < 16384){
    int c = i>>7, o = i&127;
    g_C2T[i] = c2w[o*128+c] * gpv(c2g[o]);
    return;
  } i -= 16384;
  if (i < 640){
    int which = i>>7, o = i&127;
    const float* b  = which==0?m1b: which==1?m2b: which==2?m3b: which==3?c1b:c2b;
    const float* g  = which==0?m1g: which==1?m2g: which==2?m3g: which==3?c1g:c2g;
    const float* be = which==0?m1be:which==1?m2be:which==2?m3be:which==3?c1be:c2be;
    float* dst = which==0?g_bM1: which==1?g_bM2: which==2?g_bM3: which==3?g_bC1:g_bC2;
    dst[o] = b[o]*gpv(g[o]) + be[o];
    return;
  } i -= 640;
  if (i < 384){
    int j = i>>7, o = i&127;
    g_W1x[i] = m1w[o*259 + j] * gpv(m1g[o]);
  }
}

// ---------------- launch 1: FPS ----------------
__global__ __launch_bounds__(1024) void k_fps(float* __restrict__ outAgg){
  int bk = blockIdx.x, t = threadIdx.x;
  const float* xb = g_x + bk*MM*3;
  float px = xb[t*3], py = xb[t*3+1], pz = xb[t*3+2];
  float dist = 1e10f;
  __shared__ float sc[3]; __shared__ float sv[32]; __shared__ int sw_[32]; __shared__ int sfar;
  if (t == 0) sfar = 0;
  __syncthreads();
  int lane = t & 31, wp = t >> 5;
  for (int i = 0; i < NP; i++){
    if (t == 0){
      int f = sfar;
      float cx = xb[f*3], cy = xb[f*3+1], cz = xb[f*3+2];
      sc[0]=cx; sc[1]=cy; sc[2]=cz;
      float* nz = g_newxyz + (bk*NP+i)*3; nz[0]=cx; nz[1]=cy; nz[2]=cz;
      float* oa = outAgg + (bk*NP+i)*3;   oa[0]=cx; oa[1]=cy; oa[2]=cz;
    }
    __syncthreads();
    float d = d2f(px,py,pz, sc[0],sc[1],sc[2]);
    dist = fminf(dist, d);
    float v = dist; int ix = t;
#pragma unroll
    for (int off=16; off; off>>=1){
      float ov = __shfl_down_sync(0xffffffffu, v, off);
      int   oi = __shfl_down_sync(0xffffffffu, ix, off);
      if (ov > v || (ov == v && oi < ix)){ v = ov; ix = oi; }
    }
    if (lane == 0){ sv[wp] = v; sw_[wp] = ix; }
    __syncthreads();
    if (t < 32){
      v = sv[t]; ix = sw_[t];
#pragma unroll
      for (int off=16; off; off>>=1){
        float ov = __shfl_down_sync(0xffffffffu, v, off);
        int   oi = __shfl_down_sync(0xffffffffu, ix, off);
        if (ov > v || (ov == v && oi < ix)){ v = ov; ix = oi; }
      }
      if (t == 0) sfar = ix;
    }
    __syncthreads();
  }
}

// ---------------- launch 2: fused ball (blocks 0..607) + F1 (blocks 608..911) ----
__device__ void ball_body(){
  int w = blockIdx.x*8 + (threadIdx.x >> 5);
  int lane = threadIdx.x & 31;
  int bk = w / NP;
  const float* ctr = g_newxyz + w*3;
  float cx=ctr[0], cy=ctr[1], cz=ctr[2];
  const float R2 = (float)(0.15*0.15);
  int base = w*NS;
  int cnt = 0, first = 0;
  for (int ch = 0; ch < MM/32; ch++){
    int m = ch*32 + lane;
    const float* xp = g_x + (bk*MM + m)*3;
    float d = d2f(cx,cy,cz, xp[0],xp[1],xp[2]);
    unsigned mask = __ballot_sync(0xffffffffu, d < R2);
    if (cnt == 0 && mask) first = ch*32 + __ffs(mask) - 1;
    int pos = cnt + __popc(mask & ((1u<<lane)-1u));
    if ((d < R2) && pos < NS) g_gidx[base + pos] = m;
    cnt += __popc(mask);
    if (cnt >= NS) break;
  }
  for (int j = cnt + lane; j < NS; j += 32) g_gidx[base + j] = first;
}

__device__ void f1_body(const float* __restrict__ features, float* sm){
  float* sF = sm;
  float* sW = sm + 64*128;
  int fb = blockIdx.x - 608;
  int bk = fb >> 3, mb = (fb & 7)*128;
  int b = bk / KK, k = bk % KK;
  int t = threadIdx.x;
  int s0 = (t & 15)*8, o0 = (t >> 4)*8;
  u64 acc[8][4]; zacc8(acc);
  for (int c0 = 0; c0 < CC; c0 += 64){
#pragma unroll
    for (int r = 0; r < 8; r++){
      int e4 = r*256 + t;
      int ci = e4 >> 5, mi4 = e4 & 31;
      ((float4*)sF)[e4] = *(const float4*)(features + ((size_t)(b*CC + c0 + ci)*KK + k)*MM + mb + mi4*4);
    }
#pragma unroll
    for (int r = 0; r < 8; r++){
      int e4 = r*256 + t;
      ((float4*)sW)[e4] = ((const float4*)(g_W1T + c0*128))[e4];
    }
    __syncthreads();
    gemm8x8<64>(sF, sW, acc, s0, o0);
    __syncthreads();
  }
#pragma unroll
  for (int si = 0; si < 8; si++){
    size_t row = (size_t)bk*MM + mb + s0 + si;
    u32 ov[4];
#pragma unroll
    for (int j = 0; j < 4; j++){
      float2 v = upk(acc[si][j]);
      ov[j] = h2pk(v.x, v.y);
    }
    *(uint4*)(g_F1H + row*64 + (o0>>1)) = *(uint4*)ov;
  }
}

__global__ __launch_bounds__(256) void k_ball_f1(const float* __restrict__ features){
  extern __shared__ float smdyn[];
  if (blockIdx.x < 608) ball_body();
  else                  f1_body(features, smdyn);
}

// ---------------- launch 3 (PROFILED): persistent group, fp16 HMMA ----------------
// smem: W2u[128*68] | W3u[128*68] | Hu[128*68] u32 = 104448 B; weights resident
__global__ __launch_bounds__(256, 2) void k_group(float* __restrict__ outFeat){
  extern __shared__ u32 smu[];
  u32* W2u = smu;
  u32* W3u = smu + 128*68;
  u32* Hu  = smu + 2*128*68;
  __shared__ int   sIdx[NS];
  __shared__ float sCtr[3];
  __shared__ float sWx[3*128];
  __shared__ float sB1[128], sB2[128];

  int t = threadIdx.x;
  int w = t >> 5, lane = t & 31;
  int gid = lane >> 2, tig = lane & 3;
  int m0 = (w & 3)*32, n0 = (w >> 2)*64;

  // ---- persistent prologue: weights + constants once ----
  for (int i = t; i < 2176; i += 256){
    ((uint4*)W2u)[i] = ((const uint4*)g_W2H)[i];
    ((uint4*)W3u)[i] = ((const uint4*)g_W3H)[i];
  }
  for (int i = t; i < 384; i += 256) sWx[i] = g_W1x[i];
  if (t < 128){ sB1[t]=g_bM1[t]; sB2[t]=g_bM2[t]; }

  for (int gp = blockIdx.x; gp < NGRP; gp += gridDim.x){
    int bk = gp >> 7, p = gp & 127;
    if (t < NS) sIdx[t] = g_gidx[gp*NS + t];
    if (t < 3)  sCtr[t] = g_newxyz[gp*3 + t];
    __syncthreads();

    // ---- layer 1 build: H[s][c] half2 from half2 F1 ----
    {
      int s = t >> 1, ob = (t & 1)*64;
      int m = sIdx[s];
      const float* xp = g_x + (bk*MM + m)*3;
      float gx = __fdiv_rn(__fsub_rn(xp[0], sCtr[0]), 0.15f);
      float gy = __fdiv_rn(__fsub_rn(xp[1], sCtr[1]), 0.15f);
      float gz = __fdiv_rn(__fsub_rn(xp[2], sCtr[2]), 0.15f);
      const uint4* fp = (const uint4*)(g_F1H + ((size_t)bk*MM + m)*64 + (ob>>1));
#pragma unroll
      for (int j4 = 0; j4 < 8; j4++){
        uint4 q = fp[j4];
        int o = ob + j4*8;
        float2 f0 = h2up(q.x), f1 = h2up(q.y), f2 = h2up(q.z), f3 = h2up(q.w);
        u32 ov[4];
        ov[0] = h2pk(fmaxf(f0.x + sWx[o]*gx   + sWx[128+o]*gy   + sWx[256+o]*gz   + sB1[o],   0.f),
                     fmaxf(f0.y + sWx[o+1]*gx + sWx[128+o+1]*gy + sWx[256+o+1]*gz + sB1[o+1], 0.f));
        ov[1] = h2pk(fmaxf(f1.x + sWx[o+2]*gx + sWx[128+o+2]*gy + sWx[256+o+2]*gz + sB1[o+2], 0.f),
                     fmaxf(f1.y + sWx[o+3]*gx + sWx[128+o+3]*gy + sWx[256+o+3]*gz + sB1[o+3], 0.f));
        ov[2] = h2pk(fmaxf(f2.x + sWx[o+4]*gx + sWx[128+o+4]*gy + sWx[256+o+4]*gz + sB1[o+4], 0.f),
                     fmaxf(f2.y + sWx[o+5]*gx + sWx[128+o+5]*gy + sWx[256+o+5]*gz + sB1[o+5], 0.f));
        ov[3] = h2pk(fmaxf(f3.x + sWx[o+6]*gx + sWx[128+o+6]*gy + sWx[256+o+6]*gz + sB1[o+6], 0.f),
                     fmaxf(f3.y + sWx[o+7]*gx + sWx[128+o+7]*gy + sWx[256+o+7]*gz + sB1[o+7], 0.f));
        *(uint4*)(Hu + s*68 + (ob>>1) + j4*4) = *(uint4*)ov;
      }
    }
    __syncthreads();

    float acc[2][8][4];

    // ---- GEMM 1: D1 = H * W2^T ----
#pragma unroll
    for (int mt=0;mt<2;mt++)
#pragma unroll
      for (int nt=0;nt<8;nt++)
#pragma unroll
        for (int j=0;j<4;j++) acc[mt][nt][j] = 0.f;
#pragma unroll
    for (int ks = 0; ks < 8; ks++){
      int kk = ks*8;
      u32 a[2][4];
#pragma unroll
      for (int mt = 0; mt < 2; mt++){
        int r = m0 + mt*16 + gid;
        a[mt][0] = Hu[r*68 + kk + tig];
        a[mt][1] = Hu[(r+8)*68 + kk + tig];
        a[mt][2] = Hu[r*68 + kk + 4 + tig];
        a[mt][3] = Hu[(r+8)*68 + kk + 4 + tig];
      }
#pragma unroll
      for (int nt = 0; nt < 8; nt++){
        u32 b[2];
        b[0] = W2u[(n0 + nt*8 + gid)*68 + kk + tig];
        b[1] = W2u[(n0 + nt*8 + gid)*68 + kk + 4 + tig];
        mma_f16(acc[0][nt], a[0], b);
        mma_f16(acc[1][nt], a[1], b);
      }
    }
    __syncthreads();

    // ---- epilogue: H' = fp16(relu(D1 + b2)) ----
#pragma unroll
    for (int mt = 0; mt < 2; mt++){
      int r0 = m0 + mt*16 + gid;
#pragma unroll
      for (int nt = 0; nt < 8; nt++){
        int c0 = n0 + nt*8 + 2*tig;
        int ch = (c0 >> 1);
        float b0v = sB2[c0], b1v = sB2[c0+1];
        Hu[r0*68 + ch]     = h2pk(fmaxf(acc[mt][nt][0] + b0v, 0.f), fmaxf(acc[mt][nt][1] + b1v, 0.f));
        Hu[(r0+8)*68 + ch] = h2pk(fmaxf(acc[mt][nt][2] + b0v, 0.f), fmaxf(acc[mt][nt][3] + b1v, 0.f));
      }
    }
    __syncthreads();

    // ---- GEMM 2: D2 = H' * W3^T ----
#pragma unroll
    for (int mt=0;mt<2;mt++)
#pragma unroll
      for (int nt=0;nt<8;nt++)
#pragma unroll
        for (int j=0;j<4;j++) acc[mt][nt][j] = 0.f;
#pragma unroll
    for (int ks = 0; ks < 8; ks++){
      int kk = ks*8;
      u32 a[2][4];
#pragma unroll
      for (int mt = 0; mt < 2; mt++){
        int r = m0 + mt*16 + gid;
        a[mt][0] = Hu[r*68 + kk + tig];
        a[mt][1] = Hu[(r+8)*68 + kk + tig];
        a[mt][2] = Hu[r*68 + kk + 4 + tig];
        a[mt][3] = Hu[(r+8)*68 + kk + 4 + tig];
      }
#pragma unroll
      for (int nt = 0; nt < 8; nt++){
        u32 b[2];
        b[0] = W3u[(n0 + nt*8 + gid)*68 + kk + tig];
        b[1] = W3u[(n0 + nt*8 + gid)*68 + kk + 4 + tig];
        mma_f16(acc[0][nt], a[0], b);
        mma_f16(acc[1][nt], a[1], b);
      }
    }

    // ---- maxpool over s ----
    float cm0[8], cm1[8];
#pragma unroll
    for (int nt = 0; nt < 8; nt++){
      cm0[nt] = fmaxf(fmaxf(acc[0][nt][0], acc[0][nt][2]), fmaxf(acc[1][nt][0], acc[1][nt][2]));
      cm1[nt] = fmaxf(fmaxf(acc[0][nt][1], acc[0][nt][3]), fmaxf(acc[1][nt][1], acc[1][nt][3]));
    }
#pragma unroll
    for (int off = 4; off < 32; off <<= 1){
#pragma unroll
      for (int nt = 0; nt < 8; nt++){
        cm0[nt] = fmaxf(cm0[nt], __shfl_xor_sync(0xffffffffu, cm0[nt], off));
        cm1[nt] = fmaxf(cm1[nt], __shfl_xor_sync(0xffffffffu, cm1[nt], off));
      }
    }
    __syncthreads();               // GEMM2 reads done; Hu reusable as pool buffer
    float* psm = (float*)Hu;       // [4][128]
    if (gid == 0){
#pragma unroll
      for (int nt = 0; nt < 8; nt++){
        psm[(w & 3)*128 + n0 + nt*8 + 2*tig]     = cm0[nt];
        psm[(w & 3)*128 + n0 + nt*8 + 2*tig + 1] = cm1[nt];
      }
    }
    __syncthreads();
    if (t < 128){
      float mx = fmaxf(fmaxf(psm[t], psm[128+t]), fmaxf(psm[256+t], psm[384+t]));
      float res = fmaxf(mx + g_bM3[t], 0.f);
      int fo = (bk*128 + t)*NP + p;
      g_feat[fo] = res;
      outFeat[fo] = res;
    }
    __syncthreads();               // protect sIdx/Hu before next group
  }
}

// ---------------- launch 4: c1 + c2 + head ----------------
__global__ __launch_bounds__(256) void k_c12h(const float* __restrict__ opw,
                                              const float* __restrict__ opb,
                                              float* __restrict__ outScores){
  extern __shared__ float sm[];
  float* sH = sm;
  float* sW = sm + 16384;
  __shared__ float sOp[5*128]; __shared__ float sOb[5];
  int bk = blockIdx.x, t = threadIdx.x;
  int k = bk % KK;
  for (int i = t; i < 640; i += 256) sOp[i] = opw[k*640 + i];
  if (t < 5) sOb[t] = opb[k*5 + t];
#pragma unroll
  for (int r = 0; r < 16; r++){
    ((float4*)sH)[r*256 + t] = ((const float4*)(g_feat + bk*16384))[r*256 + t];
    ((float4*)sW)[r*256 + t] = ((const float4*)g_C1T)[r*256 + t];
  }
  __syncthreads();
  int s0 = (t & 15)*8, o0 = (t >> 4)*8;
  u64 acc[8][4]; zacc8(acc);
  gemm8x8<128>(sH, sW, acc, s0, o0);
  float2 bb[4];
#pragma unroll
  for (int j = 0; j < 4; j++) bb[j] = *(const float2*)(g_bC1 + o0 + 2*j);
  __syncthreads();
#pragma unroll
  for (int si = 0; si < 8; si++)
#pragma unroll
    for (int j = 0; j < 4; j++){
      float2 v = upk(acc[si][j]);
      sH[(o0+2*j)*128 + s0+si]   = fmaxf(v.x + bb[j].x, 0.f);
      sH[(o0+2*j+1)*128 + s0+si] = fmaxf(v.y + bb[j].y, 0.f);
    }
#pragma unroll
  for (int r = 0; r < 16; r++) ((float4*)sW)[r*256 + t] = ((const float4*)g_C2T)[r*256 + t];
  __syncthreads();
  zacc8(acc);
  gemm8x8<128>(sH, sW, acc, s0, o0);
#pragma unroll
  for (int j = 0; j < 4; j++) bb[j] = *(const float2*)(g_bC2 + o0 + 2*j);
  __syncthreads();
#pragma unroll
  for (int si = 0; si < 8; si++)
#pragma unroll
    for (int j = 0; j < 4; j++){
      float2 v = upk(acc[si][j]);
      sH[(o0+2*j)*128 + s0+si]   = fmaxf(v.x + bb[j].x, 0.f);
      sH[(o0+2*j+1)*128 + s0+si] = fmaxf(v.y + bb[j].y, 0.f);
    }
  __syncthreads();
  if (t < 128){
    float a0=0,a1=0,a2=0,a3=0,a4=0;
#pragma unroll 4
    for (int c = 0; c < 128; c++){
      float nv = sH[c*128 + t];
      a0 += sOp[c]*nv; a1 += sOp[128+c]*nv; a2 += sOp[256+c]*nv; a3 += sOp[384+c]*nv; a4 += sOp[512+c]*nv;
    }
    a0+=sOb[0]; a1+=sOb[1]; a2+=sOb[2]; a3+=sOb[3]; a4+=sOb[4];
    const float* nz = g_newxyz + (bk*NP + t)*3;
    float* o = outScores + (bk*NP + t)*5;
    o[0]=a0; o[1]=a1; o[2]=nz[0]+a2; o[3]=nz[1]+a3; o[4]=nz[2]+a4;
  }
}

// ---------------- launcher ----------------
extern "C" void kernel_launch(void* const* d_in, const int* in_sizes, int n_in,
                              void* d_out, int out_size){
  (void)in_sizes; (void)n_in; (void)out_size;
  const float* xyz  = (const float*)d_in[0];
  const float* feats= (const float*)d_in[1];
  const float* m1_w = (const float*)d_in[2];
  const float* m1_b = (const float*)d_in[3];
  const float* m1_g = (const float*)d_in[4];
  const float* m1_be= (const float*)d_in[5];
  const float* m2_w = (const float*)d_in[6];
  const float* m2_b = (const float*)d_in[7];
  const float* m2_g = (const float*)d_in[8];
  const float* m2_be= (const float*)d_in[9];
  const float* m3_w = (const float*)d_in[10];
  const float* m3_b = (const float*)d_in[11];
  const float* m3_g = (const float*)d_in[12];
  const float* m3_be= (const float*)d_in[13];
  const float* c1_w = (const float*)d_in[14];
  const float* c1_b = (const float*)d_in[15];
  const float* c1_g = (const float*)d_in[16];
  const float* c1_be= (const float*)d_in[17];
  const float* c2_w = (const float*)d_in[18];
  const float* c2_b = (const float*)d_in[19];
  const float* c2_g = (const float*)d_in[20];
  const float* c2_be= (const float*)d_in[21];
  const float* op_w = (const float*)d_in[22];
  const float* op_b = (const float*)d_in[23];

  float* out = (float*)d_out;
  float* outScores = out;                 // 38*128*5
  float* outAgg    = out + 24320;         // 38*128*3
  float* outFeat   = out + 38912;         // 38*128*128

  const int GRP_SMEM = 3*128*68*4;        // 104448
  cudaFuncSetAttribute(k_ball_f1, cudaFuncAttributeMaxDynamicSharedMemorySize, 65536);
  cudaFuncSetAttribute(k_group,   cudaFuncAttributeMaxDynamicSharedMemorySize, GRP_SMEM);
  cudaFuncSetAttribute(k_c12h,    cudaFuncAttributeMaxDynamicSharedMemorySize, 131072);

  k_prep_fold<<<784, 256>>>(xyz, m1_w, m1_g, m2_w, m2_g,               // 0
      m3_w, m3_g, c1_w, c1_g, c2_w, c2_g,
      m1_b, m1_be, m2_b, m2_be, m3_b, m3_be, c1_b, c1_be, c2_b, c2_be);
  k_fps<<<BKT, 1024>>>(outAgg);                                        // 1
  k_ball_f1<<<608 + BKT*8, 256, 65536>>>(feats);                       // 2
  k_group<<<296, 256, GRP_SMEM>>>(outFeat);                            // 3 <- profiled
  k_c12h<<<BKT, 256, 131072>>>(op_w, op_b, outScores);                 // 4
}

// round 15
// speedup vs baseline: 2.4290x; 1.1416x over previous
#include <cuda_runtime.h>
#include <cuda_fp16.h>
#include <stdint.h>

typedef unsigned long long u64;
typedef uint32_t u32;

#define BB 2
#define KK 19
#define BKT 38
#define MM 1024
#define CC 256
#define NP 128
#define NS 128
#define NGRP (BKT*NP)   // 4864

// ---------------- device scratch ----------------
__device__ float g_x[BKT*MM*3];
__device__ u32   g_F1H[BKT*MM*64];   // F1 as half2 pairs (o even/odd)
__device__ float g_newxyz[BKT*NP*3];
__device__ int   g_gidx[BKT*NP*NS];
__device__ float g_feat[BKT*128*NP];
__device__ float g_W1T[CC*128];      // [c][o] fp32 (FFMA2 k_f1)
__device__ u32   g_W2H[128*68];      // [o][kk] half2 pairs along k, stride 68
__device__ u32   g_W3H[128*68];
__device__ float g_C1T[128*128];     // [c][o] fp32
__device__ float g_C2T[128*128];
__device__ float g_W1x[3*128];
__device__ float g_bM1[128], g_bM2[128], g_bM3[128], g_bC1[128], g_bC2[128];

// ---------------- fp16 helpers ----------------
__device__ __forceinline__ u32 h2pk(float a, float b){
  __half2 h = __floats2half2_rn(a, b);
  return *(u32*)&h;
}
__device__ __forceinline__ float2 h2up(u32 v){
  return __half22float2(*(__half2*)&v);
}
__device__ __forceinline__ void mma_f16(float d[4], const u32 a[4], const u32 b[2]){
  asm volatile("mma.sync.aligned.m16n8k16.row.col.f32.f16.f16.f32 "
    "{%0,%1,%2,%3}, {%4,%5,%6,%7}, {%8,%9}, {%0,%1,%2,%3};"
    : "+f"(d[0]), "+f"(d[1]), "+f"(d[2]), "+f"(d[3])
    : "r"(a[0]), "r"(a[1]), "r"(a[2]), "r"(a[3]), "r"(b[0]), "r"(b[1]));
}

// ---------------- f32x2 helpers ----------------
__device__ __forceinline__ u64 pk2(float a){ u64 r; asm("mov.b64 %0, {%1, %1};" : "=l"(r) : "f"(a)); return r; }
__device__ __forceinline__ void fma2(u64& d, u64 a, u64 b){ asm("fma.rn.f32x2 %0, %1, %2, %0;" : "+l"(d) : "l"(a), "l"(b)); }
__device__ __forceinline__ float2 upk(u64 v){ float2 r; asm("mov.b64 {%0, %1}, %2;" : "=f"(r.x), "=f"(r.y) : "l"(v)); return r; }
__device__ __forceinline__ void zacc8(u64 acc[8][4]){
#pragma unroll
  for (int i=0;i<8;i++)
#pragma unroll
    for (int j=0;j<4;j++) acc[i][j]=0ull;
}
#define GROW(i, av) { u64 a_=pk2(av); fma2(acc[i][0],a_,b0); fma2(acc[i][1],a_,b1); fma2(acc[i][2],a_,b2); fma2(acc[i][3],a_,b3); }
template<int KC>
__device__ __forceinline__ void gemm8x8(const float* sA, const float* sB, u64 acc[8][4], int s0, int o0){
#pragma unroll 4
  for (int c = 0; c < KC; c++){
    float4 a0 = *(const float4*)(sA + c*128 + s0);
    float4 a1 = *(const float4*)(sA + c*128 + s0 + 4);
    const u64* bp = (const u64*)(sB + c*128 + o0);
    u64 b0=bp[0], b1=bp[1], b2=bp[2], b3=bp[3];
    GROW(0,a0.x) GROW(1,a0.y) GROW(2,a0.z) GROW(3,a0.w)
    GROW(4,a1.x) GROW(5,a1.y) GROW(6,a1.z) GROW(7,a1.w)
  }
}

__device__ __forceinline__ float d2f(float ax,float ay,float az,float bx,float by,float bz){
  float dx=__fsub_rn(ax,bx), dy=__fsub_rn(ay,by), dz=__fsub_rn(az,bz);
  return __fadd_rn(__fadd_rn(__fmul_rn(dx,dx),__fmul_rn(dy,dy)),__fmul_rn(dz,dz));
}
__device__ __forceinline__ float gpv(float g){ return __fdiv_rn(g, sqrtf(1.0f + 1e-5f)); }

// ---------------- launch 0: prep x + fold everything ----------------
__global__ void k_prep_fold(const float* __restrict__ xyz,
                            const float* m1w, const float* m1g,
                            const float* m2w, const float* m2g,
                            const float* m3w, const float* m3g,
                            const float* c1w, const float* c1g,
                            const float* c2w, const float* c2g,
                            const float* m1b, const float* m1be,
                            const float* m2b, const float* m2be,
                            const float* m3b, const float* m3be,
                            const float* c1b, const float* c1be,
                            const float* c2b, const float* c2be){
  int i = blockIdx.x*256 + threadIdx.x;
  if (i < 116736){
    int j = i % 3, rest = i / 3;
    int m = rest % MM, bk = rest / MM;
    int b = bk / KK, k = bk % KK;
    g_x[i] = xyz[((size_t)(b*MM + m)*KK + k)*3 + j];
    return;
  } i -= 116736;
  if (i < 32768){                 // W1T [c][o]
    int c = i>>7, o = i&127;
    g_W1T[i] = m1w[o*259 + 3 + c] * gpv(m1g[o]);
    return;
  } i -= 32768;
  if (i < 8704){                  // W2H half2 pairs
    int o = i/68, kk = i%68;
    u32 v = 0;
    if (kk < 64){
      float gp = gpv(m2g[o]);
      v = h2pk(m2w[o*128 + 2*kk]*gp, m2w[o*128 + 2*kk + 1]*gp);
    }
    g_W2H[i] = v;
    return;
  } i -= 8704;
  if (i < 8704){
    int o = i/68, kk = i%68;
    u32 v = 0;
    if (kk < 64){
      float gp = gpv(m3g[o]);
      v = h2pk(m3w[o*128 + 2*kk]*gp, m3w[o*128 + 2*kk + 1]*gp);
    }
    g_W3H[i] = v;
    return;
  } i -= 8704;
  if (i < 16384){                 // C1T [c][o]
    int c = i>>7, o = i&127;
    g_C1T[i] = c1w[o*128+c] * gpv(c1g[o]);
    return;
  } i -= 16384;
  if (i < 16384){
    int c = i>>7, o = i&127;
    g_C2T[i] = c2w[o*128+c] * gpv(c2g[o]);
    return;
  } i -= 16384;
  if (i < 640){
    int which = i>>7, o = i&127;
    const float* b  = which==0?m1b: which==1?m2b: which==2?m3b: which==3?c1b:c2b;
    const float* g  = which==0?m1g: which==1?m2g: which==2?m3g: which==3?c1g:c2g;
    const float* be = which==0?m1be:which==1?m2be:which==2?m3be:which==3?c1be:c2be;
    float* dst = which==0?g_bM1: which==1?g_bM2: which==2?g_bM3: which==3?g_bC1:g_bC2;
    dst[o] = b[o]*gpv(g[o]) + be[o];
    return;
  } i -= 640;
  if (i < 384){
    int j = i>>7, o = i&127;
    g_W1x[i] = m1w[o*259 + j] * gpv(m1g[o]);
  }
}

// ---------------- launch 1: fused FPS (blocks 0..37, 256thr/4pts) + F1 (blocks 38..341) ----
__device__ void fps_body(float* __restrict__ outAgg){
  int bk = blockIdx.x, t = threadIdx.x;
  const float* xb = g_x + bk*MM*3;
  float px[4], py[4], pz[4], dist[4];
#pragma unroll
  for (int j = 0; j < 4; j++){
    int m = t + 256*j;
    px[j] = xb[m*3]; py[j] = xb[m*3+1]; pz[j] = xb[m*3+2];
    dist[j] = 1e10f;
  }
  __shared__ float sc[3]; __shared__ float sv[8]; __shared__ int si_[8]; __shared__ int sfar;
  if (t == 0) sfar = 0;
  __syncthreads();
  int lane = t & 31, wp = t >> 5;
  for (int i = 0; i < NP; i++){
    if (t == 0){
      int f = sfar;
      float cx = xb[f*3], cy = xb[f*3+1], cz = xb[f*3+2];
      sc[0]=cx; sc[1]=cy; sc[2]=cz;
      float* nz = g_newxyz + (bk*NP+i)*3; nz[0]=cx; nz[1]=cy; nz[2]=cz;
      float* oa = outAgg + (bk*NP+i)*3;   oa[0]=cx; oa[1]=cy; oa[2]=cz;
    }
    __syncthreads();
    float cx = sc[0], cy = sc[1], cz = sc[2];
    float v = -1.f; int ix = 0;
#pragma unroll
    for (int j = 0; j < 4; j++){
      float d = d2f(px[j],py[j],pz[j], cx,cy,cz);
      dist[j] = fminf(dist[j], d);
      if (dist[j] > v){ v = dist[j]; ix = t + 256*j; }   // ascending j => first-index tie-break
    }
#pragma unroll
    for (int off=16; off; off>>=1){
      float ov = __shfl_down_sync(0xffffffffu, v, off);
      int   oi = __shfl_down_sync(0xffffffffu, ix, off);
      if (ov > v || (ov == v && oi < ix)){ v = ov; ix = oi; }
    }
    if (lane == 0){ sv[wp] = v; si_[wp] = ix; }
    __syncthreads();
    if (t < 8){
      v = sv[t]; ix = si_[t];
#pragma unroll
      for (int off=4; off; off>>=1){
        float ov = __shfl_down_sync(0xffu, v, off);
        int   oi = __shfl_down_sync(0xffu, ix, off);
        if (ov > v || (ov == v && oi < ix)){ v = ov; ix = oi; }
      }
      if (t == 0) sfar = ix;
    }
    __syncthreads();
  }
}

__device__ void f1_body(const float* __restrict__ features, float* sm){
  float* sF = sm;
  float* sW = sm + 64*128;
  int fb = blockIdx.x - BKT;
  int bk = fb >> 3, mb = (fb & 7)*128;
  int b = bk / KK, k = bk % KK;
  int t = threadIdx.x;
  int s0 = (t & 15)*8, o0 = (t >> 4)*8;
  u64 acc[8][4]; zacc8(acc);
  for (int c0 = 0; c0 < CC; c0 += 64){
#pragma unroll
    for (int r = 0; r < 8; r++){
      int e4 = r*256 + t;
      int ci = e4 >> 5, mi4 = e4 & 31;
      ((float4*)sF)[e4] = *(const float4*)(features + ((size_t)(b*CC + c0 + ci)*KK + k)*MM + mb + mi4*4);
    }
#pragma unroll
    for (int r = 0; r < 8; r++){
      int e4 = r*256 + t;
      ((float4*)sW)[e4] = ((const float4*)(g_W1T + c0*128))[e4];
    }
    __syncthreads();
    gemm8x8<64>(sF, sW, acc, s0, o0);
    __syncthreads();
  }
#pragma unroll
  for (int si = 0; si < 8; si++){
    size_t row = (size_t)bk*MM + mb + s0 + si;
    u32 ov[4];
#pragma unroll
    for (int j = 0; j < 4; j++){
      float2 v = upk(acc[si][j]);
      ov[j] = h2pk(v.x, v.y);
    }
    *(uint4*)(g_F1H + row*64 + (o0>>1)) = *(uint4*)ov;
  }
}

__global__ __launch_bounds__(256) void k_fps_f1(const float* __restrict__ features,
                                                float* __restrict__ outAgg){
  extern __shared__ float smdyn[];
  if (blockIdx.x < BKT) fps_body(outAgg);
  else                  f1_body(features, smdyn);
}

// ---------------- launch 2: ball query ----------------
__global__ void k_ball(){
  int w = (blockIdx.x*blockDim.x + threadIdx.x) >> 5;
  int lane = threadIdx.x & 31;
  if (w >= BKT*NP) return;
  int bk = w / NP;
  const float* ctr = g_newxyz + w*3;
  float cx=ctr[0], cy=ctr[1], cz=ctr[2];
  const float R2 = (float)(0.15*0.15);
  int base = w*NS;
  int cnt = 0, first = 0;
  for (int ch = 0; ch < MM/32; ch++){
    int m = ch*32 + lane;
    const float* xp = g_x + (bk*MM + m)*3;
    float d = d2f(cx,cy,cz, xp[0],xp[1],xp[2]);
    unsigned mask = __ballot_sync(0xffffffffu, d < R2);
    if (cnt == 0 && mask) first = ch*32 + __ffs(mask) - 1;
    int pos = cnt + __popc(mask & ((1u<<lane)-1u));
    if ((d < R2) && pos < NS) g_gidx[base + pos] = m;
    cnt += __popc(mask);
    if (cnt >= NS) break;
  }
  for (int j = cnt + lane; j < NS; j += 32) g_gidx[base + j] = first;
}

// ---------------- launch 3 (PROFILED): persistent group, fp16 HMMA ----------------
// smem: W2u[128*68] | W3u[128*68] | Hu[128*68] u32 = 104448 B; weights resident
__global__ __launch_bounds__(256, 2) void k_group(float* __restrict__ outFeat){
  extern __shared__ u32 smu[];
  u32* W2u = smu;
  u32* W3u = smu + 128*68;
  u32* Hu  = smu + 2*128*68;
  __shared__ int   sIdx[NS];
  __shared__ float sCtr[3];
  __shared__ float sWx[3*128];
  __shared__ float sB1[128], sB2[128];

  int t = threadIdx.x;
  int w = t >> 5, lane = t & 31;
  int gid = lane >> 2, tig = lane & 3;
  int m0 = (w & 3)*32, n0 = (w >> 2)*64;

  // ---- persistent prologue: weights + constants once ----
  for (int i = t; i < 2176; i += 256){
    ((uint4*)W2u)[i] = ((const uint4*)g_W2H)[i];
    ((uint4*)W3u)[i] = ((const uint4*)g_W3H)[i];
  }
  for (int i = t; i < 384; i += 256) sWx[i] = g_W1x[i];
  if (t < 128){ sB1[t]=g_bM1[t]; sB2[t]=g_bM2[t]; }

  for (int gp = blockIdx.x; gp < NGRP; gp += gridDim.x){
    int bk = gp >> 7, p = gp & 127;
    if (t < NS) sIdx[t] = g_gidx[gp*NS + t];
    if (t < 3)  sCtr[t] = g_newxyz[gp*3 + t];
    __syncthreads();

    // ---- layer 1 build: H[s][c] half2 from half2 F1 ----
    {
      int s = t >> 1, ob = (t & 1)*64;
      int m = sIdx[s];
      const float* xp = g_x + (bk*MM + m)*3;
      float gx = __fdiv_rn(__fsub_rn(xp[0], sCtr[0]), 0.15f);
      float gy = __fdiv_rn(__fsub_rn(xp[1], sCtr[1]), 0.15f);
      float gz = __fdiv_rn(__fsub_rn(xp[2], sCtr[2]), 0.15f);
      const uint4* fp = (const uint4*)(g_F1H + ((size_t)bk*MM + m)*64 + (ob>>1));
#pragma unroll
      for (int j4 = 0; j4 < 8; j4++){
        uint4 q = fp[j4];
        int o = ob + j4*8;
        float2 f0 = h2up(q.x), f1 = h2up(q.y), f2 = h2up(q.z), f3 = h2up(q.w);
        u32 ov[4];
        ov[0] = h2pk(fmaxf(f0.x + sWx[o]*gx   + sWx[128+o]*gy   + sWx[256+o]*gz   + sB1[o],   0.f),
                     fmaxf(f0.y + sWx[o+1]*gx + sWx[128+o+1]*gy + sWx[256+o+1]*gz + sB1[o+1], 0.f));
        ov[1] = h2pk(fmaxf(f1.x + sWx[o+2]*gx + sWx[128+o+2]*gy + sWx[256+o+2]*gz + sB1[o+2], 0.f),
                     fmaxf(f1.y + sWx[o+3]*gx + sWx[128+o+3]*gy + sWx[256+o+3]*gz + sB1[o+3], 0.f));
        ov[2] = h2pk(fmaxf(f2.x + sWx[o+4]*gx + sWx[128+o+4]*gy + sWx[256+o+4]*gz + sB1[o+4], 0.f),
                     fmaxf(f2.y + sWx[o+5]*gx + sWx[128+o+5]*gy + sWx[256+o+5]*gz + sB1[o+5], 0.f));
        ov[3] = h2pk(fmaxf(f3.x + sWx[o+6]*gx + sWx[128+o+6]*gy + sWx[256+o+6]*gz + sB1[o+6], 0.f),
                     fmaxf(f3.y + sWx[o+7]*gx + sWx[128+o+7]*gy + sWx[256+o+7]*gz + sB1[o+7], 0.f));
        *(uint4*)(Hu + s*68 + (ob>>1) + j4*4) = *(uint4*)ov;
      }
    }
    __syncthreads();

    float acc[2][8][4];

    // ---- GEMM 1: D1 = H * W2^T ----
#pragma unroll
    for (int mt=0;mt<2;mt++)
#pragma unroll
      for (int nt=0;nt<8;nt++)
#pragma unroll
        for (int j=0;j<4;j++) acc[mt][nt][j] = 0.f;
#pragma unroll
    for (int ks = 0; ks < 8; ks++){
      int kk = ks*8;
      u32 a[2][4];
#pragma unroll
      for (int mt = 0; mt < 2; mt++){
        int r = m0 + mt*16 + gid;
        a[mt][0] = Hu[r*68 + kk + tig];
        a[mt][1] = Hu[(r+8)*68 + kk + tig];
        a[mt][2] = Hu[r*68 + kk + 4 + tig];
        a[mt][3] = Hu[(r+8)*68 + kk + 4 + tig];
      }
#pragma unroll
      for (int nt = 0; nt < 8; nt++){
        u32 b[2];
        b[0] = W2u[(n0 + nt*8 + gid)*68 + kk + tig];
        b[1] = W2u[(n0 + nt*8 + gid)*68 + kk + 4 + tig];
        mma_f16(acc[0][nt], a[0], b);
        mma_f16(acc[1][nt], a[1], b);
      }
    }
    __syncthreads();

    // ---- epilogue: H' = fp16(relu(D1 + b2)) ----
#pragma unroll
    for (int mt = 0; mt < 2; mt++){
      int r0 = m0 + mt*16 + gid;
#pragma unroll
      for (int nt = 0; nt < 8; nt++){
        int c0 = n0 + nt*8 + 2*tig;
        int ch = (c0 >> 1);
        float b0v = sB2[c0], b1v = sB2[c0+1];
        Hu[r0*68 + ch]     = h2pk(fmaxf(acc[mt][nt][0] + b0v, 0.f), fmaxf(acc[mt][nt][1] + b1v, 0.f));
        Hu[(r0+8)*68 + ch] = h2pk(fmaxf(acc[mt][nt][2] + b0v, 0.f), fmaxf(acc[mt][nt][3] + b1v, 0.f));
      }
    }
    __syncthreads();

    // ---- GEMM 2: D2 = H' * W3^T ----
#pragma unroll
    for (int mt=0;mt<2;mt++)
#pragma unroll
      for (int nt=0;nt<8;nt++)
#pragma unroll
        for (int j=0;j<4;j++) acc[mt][nt][j] = 0.f;
#pragma unroll
    for (int ks = 0; ks < 8; ks++){
      int kk = ks*8;
      u32 a[2][4];
#pragma unroll
      for (int mt = 0; mt < 2; mt++){
        int r = m0 + mt*16 + gid;
        a[mt][0] = Hu[r*68 + kk + tig];
        a[mt][1] = Hu[(r+8)*68 + kk + tig];
        a[mt][2] = Hu[r*68 + kk + 4 + tig];
        a[mt][3] = Hu[(r+8)*68 + kk + 4 + tig];
      }
#pragma unroll
      for (int nt = 0; nt < 8; nt++){
        u32 b[2];
        b[0] = W3u[(n0 + nt*8 + gid)*68 + kk + tig];
        b[1] = W3u[(n0 + nt*8 + gid)*68 + kk + 4 + tig];
        mma_f16(acc[0][nt], a[0], b);
        mma_f16(acc[1][nt], a[1], b);
      }
    }

    // ---- maxpool over s ----
    float cm0[8], cm1[8];
#pragma unroll
    for (int nt = 0; nt < 8; nt++){
      cm0[nt] = fmaxf(fmaxf(acc[0][nt][0], acc[0][nt][2]), fmaxf(acc[1][nt][0], acc[1][nt][2]));
      cm1[nt] = fmaxf(fmaxf(acc[0][nt][1], acc[0][nt][3]), fmaxf(acc[1][nt][1], acc[1][nt][3]));
    }
#pragma unroll
    for (int off = 4; off < 32; off <<= 1){
#pragma unroll
      for (int nt = 0; nt < 8; nt++){
        cm0[nt] = fmaxf(cm0[nt], __shfl_xor_sync(0xffffffffu, cm0[nt], off));
        cm1[nt] = fmaxf(cm1[nt], __shfl_xor_sync(0xffffffffu, cm1[nt], off));
      }
    }
    __syncthreads();               // GEMM2 reads done; Hu reusable as pool buffer
    float* psm = (float*)Hu;       // [4][128]
    if (gid == 0){
#pragma unroll
      for (int nt = 0; nt < 8; nt++){
        psm[(w & 3)*128 + n0 + nt*8 + 2*tig]     = cm0[nt];
        psm[(w & 3)*128 + n0 + nt*8 + 2*tig + 1] = cm1[nt];
      }
    }
    __syncthreads();
    if (t < 128){
      float mx = fmaxf(fmaxf(psm[t], psm[128+t]), fmaxf(psm[256+t], psm[384+t]));
      float res = fmaxf(mx + g_bM3[t], 0.f);
      int fo = (bk*128 + t)*NP + p;
      g_feat[fo] = res;
      outFeat[fo] = res;
    }
    __syncthreads();               // protect sIdx/Hu before next group
  }
}

// ---------------- launch 4: c1 + c2 + head ----------------
__global__ __launch_bounds__(256) void k_c12h(const float* __restrict__ opw,
                                              const float* __restrict__ opb,
                                              float* __restrict__ outScores){
  extern __shared__ float sm[];
  float* sH = sm;
  float* sW = sm + 16384;
  __shared__ float sOp[5*128]; __shared__ float sOb[5];
  int bk = blockIdx.x, t = threadIdx.x;
  int k = bk % KK;
  for (int i = t; i < 640; i += 256) sOp[i] = opw[k*640 + i];
  if (t < 5) sOb[t] = opb[k*5 + t];
#pragma unroll
  for (int r = 0; r < 16; r++){
    ((float4*)sH)[r*256 + t] = ((const float4*)(g_feat + bk*16384))[r*256 + t];
    ((float4*)sW)[r*256 + t] = ((const float4*)g_C1T)[r*256 + t];
  }
  __syncthreads();
  int s0 = (t & 15)*8, o0 = (t >> 4)*8;
  u64 acc[8][4]; zacc8(acc);
  gemm8x8<128>(sH, sW, acc, s0, o0);
  float2 bb[4];
#pragma unroll
  for (int j = 0; j < 4; j++) bb[j] = *(const float2*)(g_bC1 + o0 + 2*j);
  __syncthreads();
#pragma unroll
  for (int si = 0; si < 8; si++)
#pragma unroll
    for (int j = 0; j < 4; j++){
      float2 v = upk(acc[si][j]);
      sH[(o0+2*j)*128 + s0+si]   = fmaxf(v.x + bb[j].x, 0.f);
      sH[(o0+2*j+1)*128 + s0+si] = fmaxf(v.y + bb[j].y, 0.f);
    }
#pragma unroll
  for (int r = 0; r < 16; r++) ((float4*)sW)[r*256 + t] = ((const float4*)g_C2T)[r*256 + t];
  __syncthreads();
  zacc8(acc);
  gemm8x8<128>(sH, sW, acc, s0, o0);
#pragma unroll
  for (int j = 0; j < 4; j++) bb[j] = *(const float2*)(g_bC2 + o0 + 2*j);
  __syncthreads();
#pragma unroll
  for (int si = 0; si < 8; si++)
#pragma unroll
    for (int j = 0; j < 4; j++){
      float2 v = upk(acc[si][j]);
      sH[(o0+2*j)*128 + s0+si]   = fmaxf(v.x + bb[j].x, 0.f);
      sH[(o0+2*j+1)*128 + s0+si] = fmaxf(v.y + bb[j].y, 0.f);
    }
  __syncthreads();
  if (t < 128){
    float a0=0,a1=0,a2=0,a3=0,a4=0;
#pragma unroll 4
    for (int c = 0; c < 128; c++){
      float nv = sH[c*128 + t];
      a0 += sOp[c]*nv; a1 += sOp[128+c]*nv; a2 += sOp[256+c]*nv; a3 += sOp[384+c]*nv; a4 += sOp[512+c]*nv;
    }
    a0+=sOb[0]; a1+=sOb[1]; a2+=sOb[2]; a3+=sOb[3]; a4+=sOb[4];
    const float* nz = g_newxyz + (bk*NP + t)*3;
    float* o = outScores + (bk*NP + t)*5;
    o[0]=a0; o[1]=a1; o[2]=nz[0]+a2; o[3]=nz[1]+a3; o[4]=nz[2]+a4;
  }
}

// ---------------- launcher ----------------
extern "C" void kernel_launch(void* const* d_in, const int* in_sizes, int n_in,
                              void* d_out, int out_size){
  (void)in_sizes; (void)n_in; (void)out_size;
  const float* xyz  = (const float*)d_in[0];
  const float* feats= (const float*)d_in[1];
  const float* m1_w = (const float*)d_in[2];
  const float* m1_b = (const float*)d_in[3];
  const float* m1_g = (const float*)d_in[4];
  const float* m1_be= (const float*)d_in[5];
  const float* m2_w = (const float*)d_in[6];
  const float* m2_b = (const float*)d_in[7];
  const float* m2_g = (const float*)d_in[8];
  const float* m2_be= (const float*)d_in[9];
  const float* m3_w = (const float*)d_in[10];
  const float* m3_b = (const float*)d_in[11];
  const float* m3_g = (const float*)d_in[12];
  const float* m3_be= (const float*)d_in[13];
  const float* c1_w = (const float*)d_in[14];
  const float* c1_b = (const float*)d_in[15];
  const float* c1_g = (const float*)d_in[16];
  const float* c1_be= (const float*)d_in[17];
  const float* c2_w = (const float*)d_in[18];
  const float* c2_b = (const float*)d_in[19];
  const float* c2_g = (const float*)d_in[20];
  const float* c2_be= (const float*)d_in[21];
  const float* op_w = (const float*)d_in[22];
  const float* op_b = (const float*)d_in[23];

  float* out = (float*)d_out;
  float* outScores = out;                 // 38*128*5
  float* outAgg    = out + 24320;         // 38*128*3
  float* outFeat   = out + 38912;         // 38*128*128

  const int GRP_SMEM = 3*128*68*4;        // 104448
  cudaFuncSetAttribute(k_fps_f1, cudaFuncAttributeMaxDynamicSharedMemorySize, 65536);
  cudaFuncSetAttribute(k_group,  cudaFuncAttributeMaxDynamicSharedMemorySize, GRP_SMEM);
  cudaFuncSetAttribute(k_c12h,   cudaFuncAttributeMaxDynamicSharedMemorySize, 131072);

  k_prep_fold<<<784, 256>>>(xyz, m1_w, m1_g, m2_w, m2_g,               // 0
      m3_w, m3_g, c1_w, c1_g, c2_w, c2_g,
      m1_b, m1_be, m2_b, m2_be, m3_b, m3_be, c1_b, c1_be, c2_b, c2_be);
  k_fps_f1<<<BKT + BKT*8, 256, 65536>>>(feats, outAgg);                // 1
  k_ball<<<(BKT*NP*32 + 255)/256, 256>>>();                            // 2
  k_group<<<296, 256, GRP_SMEM>>>(outFeat);                            // 3 <- profiled
  k_c12h<<<BKT, 256, 131072>>>(op_w, op_b, outScores);                 // 4
}

// round 16
// speedup vs baseline: 2.4832x; 1.0223x over previous
#include <cuda_runtime.h>
#include <cuda_fp16.h>
#include <stdint.h>

typedef unsigned long long u64;
typedef uint32_t u32;

#define BB 2
#define KK 19
#define BKT 38
#define MM 1024
#define CC 256
#define NP 128
#define NS 128
#define NGRP (BKT*NP)   // 4864

// ---------------- device scratch ----------------
__device__ float g_x[BKT*MM*3];
__device__ u32   g_F1H[BKT*MM*64];   // F1 as half2 pairs (o even/odd)
__device__ float g_newxyz[BKT*NP*3];
__device__ int   g_gidx[BKT*NP*NS];
__device__ float g_feat[BKT*128*NP];
__device__ float g_W1T[CC*128];      // [c][o] fp32 (FFMA2 k_f1)
__device__ u32   g_W2H[128*68];      // [o][kk] half2 pairs along k, stride 68
__device__ u32   g_W3H[128*68];
__device__ float g_C1T[128*128];     // [c][o] fp32
__device__ float g_C2T[128*128];
__device__ float g_W1x[3*128];
__device__ float g_bM1[128], g_bM2[128], g_bM3[128], g_bC1[128], g_bC2[128];

// ---------------- fp16 helpers ----------------
__device__ __forceinline__ u32 h2pk(float a, float b){
  __half2 h = __floats2half2_rn(a, b);
  return *(u32*)&h;
}
__device__ __forceinline__ float2 h2up(u32 v){
  return __half22float2(*(__half2*)&v);
}
__device__ __forceinline__ void mma_f16(float d[4], const u32 a[4], const u32 b[2]){
  asm volatile("mma.sync.aligned.m16n8k16.row.col.f32.f16.f16.f32 "
    "{%0,%1,%2,%3}, {%4,%5,%6,%7}, {%8,%9}, {%0,%1,%2,%3};"
    : "+f"(d[0]), "+f"(d[1]), "+f"(d[2]), "+f"(d[3])
    : "r"(a[0]), "r"(a[1]), "r"(a[2]), "r"(a[3]), "r"(b[0]), "r"(b[1]));
}
__device__ __forceinline__ void ldsm_x4(u32 r[4], u32 saddr){
  asm volatile("ldmatrix.sync.aligned.m8n8.x4.shared.b16 {%0,%1,%2,%3}, [%4];"
    : "=r"(r[0]), "=r"(r[1]), "=r"(r[2]), "=r"(r[3]) : "r"(saddr));
}

// ---------------- f32x2 helpers ----------------
__device__ __forceinline__ u64 pk2(float a){ u64 r; asm("mov.b64 %0, {%1, %1};" : "=l"(r) : "f"(a)); return r; }
__device__ __forceinline__ void fma2(u64& d, u64 a, u64 b){ asm("fma.rn.f32x2 %0, %1, %2, %0;" : "+l"(d) : "l"(a), "l"(b)); }
__device__ __forceinline__ float2 upk(u64 v){ float2 r; asm("mov.b64 {%0, %1}, %2;" : "=f"(r.x), "=f"(r.y) : "l"(v)); return r; }
__device__ __forceinline__ void zacc8(u64 acc[8][4]){
#pragma unroll
  for (int i=0;i<8;i++)
#pragma unroll
    for (int j=0;j<4;j++) acc[i][j]=0ull;
}
#define GROW(i, av) { u64 a_=pk2(av); fma2(acc[i][0],a_,b0); fma2(acc[i][1],a_,b1); fma2(acc[i][2],a_,b2); fma2(acc[i][3],a_,b3); }
template<int KC>
__device__ __forceinline__ void gemm8x8(const float* sA, const float* sB, u64 acc[8][4], int s0, int o0){
#pragma unroll 4
  for (int c = 0; c < KC; c++){
    float4 a0 = *(const float4*)(sA + c*128 + s0);
    float4 a1 = *(const float4*)(sA + c*128 + s0 + 4);
    const u64* bp = (const u64*)(sB + c*128 + o0);
    u64 b0=bp[0], b1=bp[1], b2=bp[2], b3=bp[3];
    GROW(0,a0.x) GROW(1,a0.y) GROW(2,a0.z) GROW(3,a0.w)
    GROW(4,a1.x) GROW(5,a1.y) GROW(6,a1.z) GROW(7,a1.w)
  }
}

__device__ __forceinline__ float d2f(float ax,float ay,float az,float bx,float by,float bz){
  float dx=__fsub_rn(ax,bx), dy=__fsub_rn(ay,by), dz=__fsub_rn(az,bz);
  return __fadd_rn(__fadd_rn(__fmul_rn(dx,dx),__fmul_rn(dy,dy)),__fmul_rn(dz,dz));
}
__device__ __forceinline__ float gpv(float g){ return __fdiv_rn(g, sqrtf(1.0f + 1e-5f)); }

// ---------------- launch 0: prep x + fold everything ----------------
__global__ void k_prep_fold(const float* __restrict__ xyz,
                            const float* m1w, const float* m1g,
                            const float* m2w, const float* m2g,
                            const float* m3w, const float* m3g,
                            const float* c1w, const float* c1g,
                            const float* c2w, const float* c2g,
                            const float* m1b, const float* m1be,
                            const float* m2b, const float* m2be,
                            const float* m3b, const float* m3be,
                            const float* c1b, const float* c1be,
                            const float* c2b, const float* c2be){
  int i = blockIdx.x*256 + threadIdx.x;
  if (i < 116736){
    int j = i % 3, rest = i / 3;
    int m = rest % MM, bk = rest / MM;
    int b = bk / KK, k = bk % KK;
    g_x[i] = xyz[((size_t)(b*MM + m)*KK + k)*3 + j];
    return;
  } i -= 116736;
  if (i < 32768){                 // W1T [c][o]
    int c = i>>7, o = i&127;
    g_W1T[i] = m1w[o*259 + 3 + c] * gpv(m1g[o]);
    return;
  } i -= 32768;
  if (i < 8704){                  // W2H half2 pairs
    int o = i/68, kk = i%68;
    u32 v = 0;
    if (kk < 64){
      float gp = gpv(m2g[o]);
      v = h2pk(m2w[o*128 + 2*kk]*gp, m2w[o*128 + 2*kk + 1]*gp);
    }
    g_W2H[i] = v;
    return;
  } i -= 8704;
  if (i < 8704){
    int o = i/68, kk = i%68;
    u32 v = 0;
    if (kk < 64){
      float gp = gpv(m3g[o]);
      v = h2pk(m3w[o*128 + 2*kk]*gp, m3w[o*128 + 2*kk + 1]*gp);
    }
    g_W3H[i] = v;
    return;
  } i -= 8704;
  if (i < 16384){                 // C1T [c][o]
    int c = i>>7, o = i&127;
    g_C1T[i] = c1w[o*128+c] * gpv(c1g[o]);
    return;
  } i -= 16384;
  if (i < 16384){
    int c = i>>7, o = i&127;
    g_C2T[i] = c2w[o*128+c] * gpv(c2g[o]);
    return;
  } i -= 16384;
  if (i < 640){
    int which = i>>7, o = i&127;
    const float* b  = which==0?m1b: which==1?m2b: which==2?m3b: which==3?c1b:c2b;
    const float* g  = which==0?m1g: which==1?m2g: which==2?m3g: which==3?c1g:c2g;
    const float* be = which==0?m1be:which==1?m2be:which==2?m3be:which==3?c1be:c2be;
    float* dst = which==0?g_bM1: which==1?g_bM2: which==2?g_bM3: which==3?g_bC1:g_bC2;
    dst[o] = b[o]*gpv(g[o]) + be[o];
    return;
  } i -= 640;
  if (i < 384){
    int j = i>>7, o = i&127;
    g_W1x[i] = m1w[o*259 + j] * gpv(m1g[o]);
  }
}

// ---------------- launch 1: fused FPS (blocks 0..37) + F1 (blocks 38..341) ----
__device__ void fps_body(float* __restrict__ outAgg){
  int bk = blockIdx.x, t = threadIdx.x;
  const float* xb = g_x + bk*MM*3;
  float px[4], py[4], pz[4], dist[4];
#pragma unroll
  for (int j = 0; j < 4; j++){
    int m = t + 256*j;
    px[j] = xb[m*3]; py[j] = xb[m*3+1]; pz[j] = xb[m*3+2];
    dist[j] = 1e10f;
  }
  __shared__ float sc[3]; __shared__ float sv[8]; __shared__ int si_[8]; __shared__ int sfar;
  if (t == 0) sfar = 0;
  __syncthreads();
  int lane = t & 31, wp = t >> 5;
  for (int i = 0; i < NP; i++){
    if (t == 0){
      int f = sfar;
      float cx = xb[f*3], cy = xb[f*3+1], cz = xb[f*3+2];
      sc[0]=cx; sc[1]=cy; sc[2]=cz;
      float* nz = g_newxyz + (bk*NP+i)*3; nz[0]=cx; nz[1]=cy; nz[2]=cz;
      float* oa = outAgg + (bk*NP+i)*3;   oa[0]=cx; oa[1]=cy; oa[2]=cz;
    }
    __syncthreads();
    float cx = sc[0], cy = sc[1], cz = sc[2];
    float v = -1.f; int ix = 0;
#pragma unroll
    for (int j = 0; j < 4; j++){
      float d = d2f(px[j],py[j],pz[j], cx,cy,cz);
      dist[j] = fminf(dist[j], d);
      if (dist[j] > v){ v = dist[j]; ix = t + 256*j; }
    }
#pragma unroll
    for (int off=16; off; off>>=1){
      float ov = __shfl_down_sync(0xffffffffu, v, off);
      int   oi = __shfl_down_sync(0xffffffffu, ix, off);
      if (ov > v || (ov == v && oi < ix)){ v = ov; ix = oi; }
    }
    if (lane == 0){ sv[wp] = v; si_[wp] = ix; }
    __syncthreads();
    if (t < 8){
      v = sv[t]; ix = si_[t];
#pragma unroll
      for (int off=4; off; off>>=1){
        float ov = __shfl_down_sync(0xffu, v, off);
        int   oi = __shfl_down_sync(0xffu, ix, off);
        if (ov > v || (ov == v && oi < ix)){ v = ov; ix = oi; }
      }
      if (t == 0) sfar = ix;
    }
    __syncthreads();
  }
}

__device__ void f1_body(const float* __restrict__ features, float* sm){
  float* sF = sm;
  float* sW = sm + 64*128;
  int fb = blockIdx.x - BKT;
  int bk = fb >> 3, mb = (fb & 7)*128;
  int b = bk / KK, k = bk % KK;
  int t = threadIdx.x;
  int s0 = (t & 15)*8, o0 = (t >> 4)*8;
  u64 acc[8][4]; zacc8(acc);
  for (int c0 = 0; c0 < CC; c0 += 64){
#pragma unroll
    for (int r = 0; r < 8; r++){
      int e4 = r*256 + t;
      int ci = e4 >> 5, mi4 = e4 & 31;
      ((float4*)sF)[e4] = *(const float4*)(features + ((size_t)(b*CC + c0 + ci)*KK + k)*MM + mb + mi4*4);
    }
#pragma unroll
    for (int r = 0; r < 8; r++){
      int e4 = r*256 + t;
      ((float4*)sW)[e4] = ((const float4*)(g_W1T + c0*128))[e4];
    }
    __syncthreads();
    gemm8x8<64>(sF, sW, acc, s0, o0);
    __syncthreads();
  }
#pragma unroll
  for (int si = 0; si < 8; si++){
    size_t row = (size_t)bk*MM + mb + s0 + si;
    u32 ov[4];
#pragma unroll
    for (int j = 0; j < 4; j++){
      float2 v = upk(acc[si][j]);
      ov[j] = h2pk(v.x, v.y);
    }
    *(uint4*)(g_F1H + row*64 + (o0>>1)) = *(uint4*)ov;
  }
}

__global__ __launch_bounds__(256) void k_fps_f1(const float* __restrict__ features,
                                                float* __restrict__ outAgg){
  extern __shared__ float smdyn[];
  if (blockIdx.x < BKT) fps_body(outAgg);
  else                  f1_body(features, smdyn);
}

// ---------------- launch 2: ball query ----------------
__global__ void k_ball(){
  int w = (blockIdx.x*blockDim.x + threadIdx.x) >> 5;
  int lane = threadIdx.x & 31;
  if (w >= BKT*NP) return;
  int bk = w / NP;
  const float* ctr = g_newxyz + w*3;
  float cx=ctr[0], cy=ctr[1], cz=ctr[2];
  const float R2 = (float)(0.15*0.15);
  int base = w*NS;
  int cnt = 0, first = 0;
  for (int ch = 0; ch < MM/32; ch++){
    int m = ch*32 + lane;
    const float* xp = g_x + (bk*MM + m)*3;
    float d = d2f(cx,cy,cz, xp[0],xp[1],xp[2]);
    unsigned mask = __ballot_sync(0xffffffffu, d < R2);
    if (cnt == 0 && mask) first = ch*32 + __ffs(mask) - 1;
    int pos = cnt + __popc(mask & ((1u<<lane)-1u));
    if ((d < R2) && pos < NS) g_gidx[base + pos] = m;
    cnt += __popc(mask);
    if (cnt >= NS) break;
  }
  for (int j = cnt + lane; j < NS; j += 32) g_gidx[base + j] = first;
}

// ---------------- launch 3 (PROFILED): persistent group, fp16 HMMA + ldmatrix ----
// smem: W2u[128*68] | W3u[128*68] | Hu[128*68] u32 = 104448 B; weights resident
__global__ __launch_bounds__(256, 2) void k_group(float* __restrict__ outFeat){
  extern __shared__ u32 smu[];
  u32* W2u = smu;
  u32* W3u = smu + 128*68;
  u32* Hu  = smu + 2*128*68;
  __shared__ int   sIdx[NS];
  __shared__ float sCtr[3];
  __shared__ float sWx[3*128];
  __shared__ float sB1[128], sB2[128];

  int t = threadIdx.x;
  int w = t >> 5, lane = t & 31;
  int gid = lane >> 2, tig = lane & 3;
  int m0 = (w & 3)*32, n0 = (w >> 2)*64;

  // ldmatrix per-lane bases (u32-element indices)
  int lg = lane >> 3, rr = lane & 7;
  // A: tile order a0..a3 = (m-lo,k-lo)(m-hi,k-lo)(m-lo,k-hi)(m-hi,k-hi)
  u32 aIdx = (u32)((m0 + ((lg & 1) << 3) + rr)*68 + ((lg >> 1) << 2));
  // B: tile order = (nt',b0)(nt',b1)(nt'+1,b0)(nt'+1,b1)
  u32 bIdx = (u32)((n0 + ((lg >> 1) << 3) + rr)*68 + ((lg & 1) << 2));

  u32 HuS  = (u32)__cvta_generic_to_shared(Hu);
  u32 W2S  = (u32)__cvta_generic_to_shared(W2u);
  u32 W3S  = (u32)__cvta_generic_to_shared(W3u);

  // ---- persistent prologue: weights + constants once ----
  for (int i = t; i < 2176; i += 256){
    ((uint4*)W2u)[i] = ((const uint4*)g_W2H)[i];
    ((uint4*)W3u)[i] = ((const uint4*)g_W3H)[i];
  }
  for (int i = t; i < 384; i += 256) sWx[i] = g_W1x[i];
  if (t < 128){ sB1[t]=g_bM1[t]; sB2[t]=g_bM2[t]; }

  for (int gp = blockIdx.x; gp < NGRP; gp += gridDim.x){
    int bk = gp >> 7, p = gp & 127;
    if (t < NS) sIdx[t] = g_gidx[gp*NS + t];
    if (t < 3)  sCtr[t] = g_newxyz[gp*3 + t];
    __syncthreads();

    // ---- layer 1 build: H[s][c] half2 from half2 F1 ----
    {
      int s = t >> 1, ob = (t & 1)*64;
      int m = sIdx[s];
      const float* xp = g_x + (bk*MM + m)*3;
      float gx = __fdiv_rn(__fsub_rn(xp[0], sCtr[0]), 0.15f);
      float gy = __fdiv_rn(__fsub_rn(xp[1], sCtr[1]), 0.15f);
      float gz = __fdiv_rn(__fsub_rn(xp[2], sCtr[2]), 0.15f);
      const uint4* fp = (const uint4*)(g_F1H + ((size_t)bk*MM + m)*64 + (ob>>1));
#pragma unroll
      for (int j4 = 0; j4 < 8; j4++){
        uint4 q = fp[j4];
        int o = ob + j4*8;
        float2 f0 = h2up(q.x), f1 = h2up(q.y), f2 = h2up(q.z), f3 = h2up(q.w);
        u32 ov[4];
        ov[0] = h2pk(fmaxf(f0.x + sWx[o]*gx   + sWx[128+o]*gy   + sWx[256+o]*gz   + sB1[o],   0.f),
                     fmaxf(f0.y + sWx[o+1]*gx + sWx[128+o+1]*gy + sWx[256+o+1]*gz + sB1[o+1], 0.f));
        ov[1] = h2pk(fmaxf(f1.x + sWx[o+2]*gx + sWx[128+o+2]*gy + sWx[256+o+2]*gz + sB1[o+2], 0.f),
                     fmaxf(f1.y + sWx[o+3]*gx + sWx[128+o+3]*gy + sWx[256+o+3]*gz + sB1[o+3], 0.f));
        ov[2] = h2pk(fmaxf(f2.x + sWx[o+4]*gx + sWx[128+o+4]*gy + sWx[256+o+4]*gz + sB1[o+4], 0.f),
                     fmaxf(f2.y + sWx[o+5]*gx + sWx[128+o+5]*gy + sWx[256+o+5]*gz + sB1[o+5], 0.f));
        ov[3] = h2pk(fmaxf(f3.x + sWx[o+6]*gx + sWx[128+o+6]*gy + sWx[256+o+6]*gz + sB1[o+6], 0.f),
                     fmaxf(f3.y + sWx[o+7]*gx + sWx[128+o+7]*gy + sWx[256+o+7]*gz + sB1[o+7], 0.f));
        *(uint4*)(Hu + s*68 + (ob>>1) + j4*4) = *(uint4*)ov;
      }
    }
    __syncthreads();

    float acc[2][8][4];

    // ---- GEMM 1: D1 = H * W2^T (ldmatrix) ----
#pragma unroll
    for (int mt=0;mt<2;mt++)
#pragma unroll
      for (int nt=0;nt<8;nt++)
#pragma unroll
        for (int j=0;j<4;j++) acc[mt][nt][j] = 0.f;
#pragma unroll
    for (int ks = 0; ks < 8; ks++){
      u32 kb = (u32)(ks*8*4);
      u32 a[2][4];
      ldsm_x4(a[0], HuS + aIdx*4 + kb);
      ldsm_x4(a[1], HuS + (aIdx + 16*68)*4 + kb);
#pragma unroll
      for (int pr = 0; pr < 4; pr++){
        u32 r[4];
        ldsm_x4(r, W2S + (bIdx + (u32)(pr*16*68))*4 + kb);
        mma_f16(acc[0][2*pr],   a[0], &r[0]);
        mma_f16(acc[1][2*pr],   a[1], &r[0]);
        mma_f16(acc[0][2*pr+1], a[0], &r[2]);
        mma_f16(acc[1][2*pr+1], a[1], &r[2]);
      }
    }
    __syncthreads();

    // ---- epilogue: H' = fp16(relu(D1 + b2)) ----
#pragma unroll
    for (int mt = 0; mt < 2; mt++){
      int r0 = m0 + mt*16 + gid;
#pragma unroll
      for (int nt = 0; nt < 8; nt++){
        int c0 = n0 + nt*8 + 2*tig;
        int ch = (c0 >> 1);
        float b0v = sB2[c0], b1v = sB2[c0+1];
        Hu[r0*68 + ch]     = h2pk(fmaxf(acc[mt][nt][0] + b0v, 0.f), fmaxf(acc[mt][nt][1] + b1v, 0.f));
        Hu[(r0+8)*68 + ch] = h2pk(fmaxf(acc[mt][nt][2] + b0v, 0.f), fmaxf(acc[mt][nt][3] + b1v, 0.f));
      }
    }
    __syncthreads();

    // ---- GEMM 2: D2 = H' * W3^T (ldmatrix) ----
#pragma unroll
    for (int mt=0;mt<2;mt++)
#pragma unroll
      for (int nt=0;nt<8;nt++)
#pragma unroll
        for (int j=0;j<4;j++) acc[mt][nt][j] = 0.f;
#pragma unroll
    for (int ks = 0; ks < 8; ks++){
      u32 kb = (u32)(ks*8*4);
      u32 a[2][4];
      ldsm_x4(a[0], HuS + aIdx*4 + kb);
      ldsm_x4(a[1], HuS + (aIdx + 16*68)*4 + kb);
#pragma unroll
      for (int pr = 0; pr < 4; pr++){
        u32 r[4];
        ldsm_x4(r, W3S + (bIdx + (u32)(pr*16*68))*4 + kb);
        mma_f16(acc[0][2*pr],   a[0], &r[0]);
        mma_f16(acc[1][2*pr],   a[1], &r[0]);
        mma_f16(acc[0][2*pr+1], a[0], &r[2]);
        mma_f16(acc[1][2*pr+1], a[1], &r[2]);
      }
    }

    // ---- maxpool over s ----
    float cm0[8], cm1[8];
#pragma unroll
    for (int nt = 0; nt < 8; nt++){
      cm0[nt] = fmaxf(fmaxf(acc[0][nt][0], acc[0][nt][2]), fmaxf(acc[1][nt][0], acc[1][nt][2]));
      cm1[nt] = fmaxf(fmaxf(acc[0][nt][1], acc[0][nt][3]), fmaxf(acc[1][nt][1], acc[1][nt][3]));
    }
#pragma unroll
    for (int off = 4; off < 32; off <<= 1){
#pragma unroll
      for (int nt = 0; nt < 8; nt++){
        cm0[nt] = fmaxf(cm0[nt], __shfl_xor_sync(0xffffffffu, cm0[nt], off));
        cm1[nt] = fmaxf(cm1[nt], __shfl_xor_sync(0xffffffffu, cm1[nt], off));
      }
    }
    __syncthreads();               // GEMM2 reads done; Hu reusable as pool buffer
    float* psm = (float*)Hu;       // [4][128]
    if (gid == 0){
#pragma unroll
      for (int nt = 0; nt < 8; nt++){
        psm[(w & 3)*128 + n0 + nt*8 + 2*tig]     = cm0[nt];
        psm[(w & 3)*128 + n0 + nt*8 + 2*tig + 1] = cm1[nt];
      }
    }
    __syncthreads();
    if (t < 128){
      float mx = fmaxf(fmaxf(psm[t], psm[128+t]), fmaxf(psm[256+t], psm[384+t]));
      float res = fmaxf(mx + g_bM3[t], 0.f);
      int fo = (bk*128 + t)*NP + p;
      g_feat[fo] = res;
      outFeat[fo] = res;
    }
    __syncthreads();               // protect sIdx/Hu before next group
  }
}

// ---------------- launch 4: c1 + c2 + head ----------------
__global__ __launch_bounds__(256) void k_c12h(const float* __restrict__ opw,
                                              const float* __restrict__ opb,
                                              float* __restrict__ outScores){
  extern __shared__ float sm[];
  float* sH = sm;
  float* sW = sm + 16384;
  __shared__ float sOp[5*128]; __shared__ float sOb[5];
  int bk = blockIdx.x, t = threadIdx.x;
  int k = bk % KK;
  for (int i = t; i < 640; i += 256) sOp[i] = opw[k*640 + i];
  if (t < 5) sOb[t] = opb[k*5 + t];
#pragma unroll
  for (int r = 0; r < 16; r++){
    ((float4*)sH)[r*256 + t] = ((const float4*)(g_feat + bk*16384))[r*256 + t];
    ((float4*)sW)[r*256 + t] = ((const float4*)g_C1T)[r*256 + t];
  }
  __syncthreads();
  int s0 = (t & 15)*8, o0 = (t >> 4)*8;
  u64 acc[8][4]; zacc8(acc);
  gemm8x8<128>(sH, sW, acc, s0, o0);
  float2 bb[4];
#pragma unroll
  for (int j = 0; j < 4; j++) bb[j] = *(const float2*)(g_bC1 + o0 + 2*j);
  __syncthreads();
#pragma unroll
  for (int si = 0; si < 8; si++)
#pragma unroll
    for (int j = 0; j < 4; j++){
      float2 v = upk(acc[si][j]);
      sH[(o0+2*j)*128 + s0+si]   = fmaxf(v.x + bb[j].x, 0.f);
      sH[(o0+2*j+1)*128 + s0+si] = fmaxf(v.y + bb[j].y, 0.f);
    }
#pragma unroll
  for (int r = 0; r < 16; r++) ((float4*)sW)[r*256 + t] = ((const float4*)g_C2T)[r*256 + t];
  __syncthreads();
  zacc8(acc);
  gemm8x8<128>(sH, sW, acc, s0, o0);
#pragma unroll
  for (int j = 0; j < 4; j++) bb[j] = *(const float2*)(g_bC2 + o0 + 2*j);
  __syncthreads();
#pragma unroll
  for (int si = 0; si < 8; si++)
#pragma unroll
    for (int j = 0; j < 4; j++){
      float2 v = upk(acc[si][j]);
      sH[(o0+2*j)*128 + s0+si]   = fmaxf(v.x + bb[j].x, 0.f);
      sH[(o0+2*j+1)*128 + s0+si] = fmaxf(v.y + bb[j].y, 0.f);
    }
  __syncthreads();
  if (t < 128){
    float a0=0,a1=0,a2=0,a3=0,a4=0;
#pragma unroll 4
    for (int c = 0; c < 128; c++){
      float nv = sH[c*128 + t];
      a0 += sOp[c]*nv; a1 += sOp[128+c]*nv; a2 += sOp[256+c]*nv; a3 += sOp[384+c]*nv; a4 += sOp[512+c]*nv;
    }
    a0+=sOb[0]; a1+=sOb[1]; a2+=sOb[2]; a3+=sOb[3]; a4+=sOb[4];
    const float* nz = g_newxyz + (bk*NP + t)*3;
    float* o = outScores + (bk*NP + t)*5;
    o[0]=a0; o[1]=a1; o[2]=nz[0]+a2; o[3]=nz[1]+a3; o[4]=nz[2]+a4;
  }
}

// ---------------- launcher ----------------
extern "C" void kernel_launch(void* const* d_in, const int* in_sizes, int n_in,
                              void* d_out, int out_size){
  (void)in_sizes; (void)n_in; (void)out_size;
  const float* xyz  = (const float*)d_in[0];
  const float* feats= (const float*)d_in[1];
  const float* m1_w = (const float*)d_in[2];
  const float* m1_b = (const float*)d_in[3];
  const float* m1_g = (const float*)d_in[4];
  const float* m1_be= (const float*)d_in[5];
  const float* m2_w = (const float*)d_in[6];
  const float* m2_b = (const float*)d_in[7];
  const float* m2_g = (const float*)d_in[8];
  const float* m2_be= (const float*)d_in[9];
  const float* m3_w = (const float*)d_in[10];
  const float* m3_b = (const float*)d_in[11];
  const float* m3_g = (const float*)d_in[12];
  const float* m3_be= (const float*)d_in[13];
  const float* c1_w = (const float*)d_in[14];
  const float* c1_b = (const float*)d_in[15];
  const float* c1_g = (const float*)d_in[16];
  const float* c1_be= (const float*)d_in[17];
  const float* c2_w = (const float*)d_in[18];
  const float* c2_b = (const float*)d_in[19];
  const float* c2_g = (const float*)d_in[20];
  const float* c2_be= (const float*)d_in[21];
  const float* op_w = (const float*)d_in[22];
  const float* op_b = (const float*)d_in[23];

  float* out = (float*)d_out;
  float* outScores = out;                 // 38*128*5
  float* outAgg    = out + 24320;         // 38*128*3
  float* outFeat   = out + 38912;         // 38*128*128

  const int GRP_SMEM = 3*128*68*4;        // 104448
  cudaFuncSetAttribute(k_fps_f1, cudaFuncAttributeMaxDynamicSharedMemorySize, 65536);
  cudaFuncSetAttribute(k_group,  cudaFuncAttributeMaxDynamicSharedMemorySize, GRP_SMEM);
  cudaFuncSetAttribute(k_c12h,   cudaFuncAttributeMaxDynamicSharedMemorySize, 131072);

  k_prep_fold<<<784, 256>>>(xyz, m1_w, m1_g, m2_w, m2_g,               // 0
      m3_w, m3_g, c1_w, c1_g, c2_w, c2_g,
      m1_b, m1_be, m2_b, m2_be, m3_b, m3_be, c1_b, c1_be, c2_b, c2_be);
  k_fps_f1<<<BKT + BKT*8, 256, 65536>>>(feats, outAgg);                // 1
  k_ball<<<(BKT*NP*32 + 255)/256, 256>>>();                            // 2
  k_group<<<296, 256, GRP_SMEM>>>(outFeat);                            // 3 <- profiled
  k_c12h<<<BKT, 256, 131072>>>(op_w, op_b, outScores);                 // 4
}

// round 17
// speedup vs baseline: 2.5705x; 1.0352x over previous
#include <cuda_runtime.h>
#include <cuda_fp16.h>
#include <stdint.h>

typedef unsigned long long u64;
typedef uint32_t u32;

#define BB 2
#define KK 19
#define BKT 38
#define MM 1024
#define CC 256
#define NP 128
#define NS 128
#define NGRP (BKT*NP)   // 4864

// ---------------- device scratch ----------------
__device__ float g_x[BKT*MM*3];
__device__ u32   g_F1H[BKT*MM*64];   // F1 as half2 pairs (o even/odd)
__device__ float g_newxyz[BKT*NP*3];
__device__ int   g_gidx[BKT*NP*NS];
__device__ float g_feat[BKT*128*NP];
__device__ u32   g_W1HF[128*132];    // [o][kk] half2 pairs along c, stride 132 (k-frag layout)
__device__ u32   g_W2H[128*68];      // [o][kk] half2 pairs along k, stride 68
__device__ u32   g_W3H[128*68];
__device__ float g_C1T[128*128];     // [c][o] fp32
__device__ float g_C2T[128*128];
__device__ float g_W1x[3*128];
__device__ float g_bM1[128], g_bM2[128], g_bM3[128], g_bC1[128], g_bC2[128];

// ---------------- fp16 helpers ----------------
__device__ __forceinline__ u32 h2pk(float a, float b){
  __half2 h = __floats2half2_rn(a, b);
  return *(u32*)&h;
}
__device__ __forceinline__ float2 h2up(u32 v){
  return __half22float2(*(__half2*)&v);
}
__device__ __forceinline__ void mma_f16(float d[4], const u32 a[4], const u32 b[2]){
  asm volatile("mma.sync.aligned.m16n8k16.row.col.f32.f16.f16.f32 "
    "{%0,%1,%2,%3}, {%4,%5,%6,%7}, {%8,%9}, {%0,%1,%2,%3};"
    : "+f"(d[0]), "+f"(d[1]), "+f"(d[2]), "+f"(d[3])
    : "r"(a[0]), "r"(a[1]), "r"(a[2]), "r"(a[3]), "r"(b[0]), "r"(b[1]));
}
__device__ __forceinline__ void ldsm_x4(u32 r[4], u32 saddr){
  asm volatile("ldmatrix.sync.aligned.m8n8.x4.shared.b16 {%0,%1,%2,%3}, [%4];"
    : "=r"(r[0]), "=r"(r[1]), "=r"(r[2]), "=r"(r[3]) : "r"(saddr));
}
__device__ __forceinline__ void ldsm_x4_t(u32 r[4], u32 saddr){
  asm volatile("ldmatrix.sync.aligned.m8n8.x4.trans.shared.b16 {%0,%1,%2,%3}, [%4];"
    : "=r"(r[0]), "=r"(r[1]), "=r"(r[2]), "=r"(r[3]) : "r"(saddr));
}

// ---------------- f32x2 helpers (k_c12h) ----------------
__device__ __forceinline__ u64 pk2(float a){ u64 r; asm("mov.b64 %0, {%1, %1};" : "=l"(r) : "f"(a)); return r; }
__device__ __forceinline__ void fma2(u64& d, u64 a, u64 b){ asm("fma.rn.f32x2 %0, %1, %2, %0;" : "+l"(d) : "l"(a), "l"(b)); }
__device__ __forceinline__ float2 upk(u64 v){ float2 r; asm("mov.b64 {%0, %1}, %2;" : "=f"(r.x), "=f"(r.y) : "l"(v)); return r; }
__device__ __forceinline__ void zacc8(u64 acc[8][4]){
#pragma unroll
  for (int i=0;i<8;i++)
#pragma unroll
    for (int j=0;j<4;j++) acc[i][j]=0ull;
}
#define GROW(i, av) { u64 a_=pk2(av); fma2(acc[i][0],a_,b0); fma2(acc[i][1],a_,b1); fma2(acc[i][2],a_,b2); fma2(acc[i][3],a_,b3); }
template<int KC>
__device__ __forceinline__ void gemm8x8(const float* sA, const float* sB, u64 acc[8][4], int s0, int o0){
#pragma unroll 4
  for (int c = 0; c < KC; c++){
    float4 a0 = *(const float4*)(sA + c*128 + s0);
    float4 a1 = *(const float4*)(sA + c*128 + s0 + 4);
    const u64* bp = (const u64*)(sB + c*128 + o0);
    u64 b0=bp[0], b1=bp[1], b2=bp[2], b3=bp[3];
    GROW(0,a0.x) GROW(1,a0.y) GROW(2,a0.z) GROW(3,a0.w)
    GROW(4,a1.x) GROW(5,a1.y) GROW(6,a1.z) GROW(7,a1.w)
  }
}

__device__ __forceinline__ float d2f(float ax,float ay,float az,float bx,float by,float bz){
  float dx=__fsub_rn(ax,bx), dy=__fsub_rn(ay,by), dz=__fsub_rn(az,bz);
  return __fadd_rn(__fadd_rn(__fmul_rn(dx,dx),__fmul_rn(dy,dy)),__fmul_rn(dz,dz));
}
__device__ __forceinline__ float gpv(float g){ return __fdiv_rn(g, sqrtf(1.0f + 1e-5f)); }

// ---------------- launch 0: prep x + fold everything ----------------
// prep_x 116736 | W1HF 16896 | W2H 8704 | W3H 8704 | C1T 16384 | C2T 16384 | bias 640 | W1x 384 = 184832
__global__ void k_prep_fold(const float* __restrict__ xyz,
                            const float* m1w, const float* m1g,
                            const float* m2w, const float* m2g,
                            const float* m3w, const float* m3g,
                            const float* c1w, const float* c1g,
                            const float* c2w, const float* c2g,
                            const float* m1b, const float* m1be,
                            const float* m2b, const float* m2be,
                            const float* m3b, const float* m3be,
                            const float* c1b, const float* c1be,
                            const float* c2b, const float* c2be){
  int i = blockIdx.x*256 + threadIdx.x;
  if (i < 116736){
    int j = i % 3, rest = i / 3;
    int m = rest % MM, bk = rest / MM;
    int b = bk / KK, k = bk % KK;
    g_x[i] = xyz[((size_t)(b*MM + m)*KK + k)*3 + j];
    return;
  } i -= 116736;
  if (i < 16896){                 // W1HF half2 pairs, stride 132
    int o = i/132, kk = i%132;
    u32 v = 0;
    if (kk < 128){
      float gp = gpv(m1g[o]);
      v = h2pk(m1w[o*259 + 3 + 2*kk]*gp, m1w[o*259 + 3 + 2*kk + 1]*gp);
    }
    g_W1HF[i] = v;
    return;
  } i -= 16896;
  if (i < 8704){                  // W2H half2 pairs
    int o = i/68, kk = i%68;
    u32 v = 0;
    if (kk < 64){
      float gp = gpv(m2g[o]);
      v = h2pk(m2w[o*128 + 2*kk]*gp, m2w[o*128 + 2*kk + 1]*gp);
    }
    g_W2H[i] = v;
    return;
  } i -= 8704;
  if (i < 8704){
    int o = i/68, kk = i%68;
    u32 v = 0;
    if (kk < 64){
      float gp = gpv(m3g[o]);
      v = h2pk(m3w[o*128 + 2*kk]*gp, m3w[o*128 + 2*kk + 1]*gp);
    }
    g_W3H[i] = v;
    return;
  } i -= 8704;
  if (i < 16384){                 // C1T [c][o]
    int c = i>>7, o = i&127;
    g_C1T[i] = c1w[o*128+c] * gpv(c1g[o]);
    return;
  } i -= 16384;
  if (i < 16384){
    int c = i>>7, o = i&127;
    g_C2T[i] = c2w[o*128+c] * gpv(c2g[o]);
    return;
  } i -= 16384;
  if (i < 640){
    int which = i>>7, o = i&127;
    const float* b  = which==0?m1b: which==1?m2b: which==2?m3b: which==3?c1b:c2b;
    const float* g  = which==0?m1g: which==1?m2g: which==2?m3g: which==3?c1g:c2g;
    const float* be = which==0?m1be:which==1?m2be:which==2?m3be:which==3?c1be:c2be;
    float* dst = which==0?g_bM1: which==1?g_bM2: which==2?g_bM3: which==3?g_bC1:g_bC2;
    dst[o] = b[o]*gpv(g[o]) + be[o];
    return;
  } i -= 640;
  if (i < 384){
    int j = i>>7, o = i&127;
    g_W1x[i] = m1w[o*259 + j] * gpv(m1g[o]);
  }
}

// ---------------- launch 1: fused FPS (blocks 0..37) + F1-mma (blocks 38..341) ----
__device__ void fps_body(float* __restrict__ outAgg){
  int bk = blockIdx.x, t = threadIdx.x;
  const float* xb = g_x + bk*MM*3;
  float px[4], py[4], pz[4], dist[4];
#pragma unroll
  for (int j = 0; j < 4; j++){
    int m = t + 256*j;
    px[j] = xb[m*3]; py[j] = xb[m*3+1]; pz[j] = xb[m*3+2];
    dist[j] = 1e10f;
  }
  __shared__ float sc[3]; __shared__ float sv[8]; __shared__ int si_[8]; __shared__ int sfar;
  if (t == 0) sfar = 0;
  __syncthreads();
  int lane = t & 31, wp = t >> 5;
  for (int i = 0; i < NP; i++){
    if (t == 0){
      int f = sfar;
      float cx = xb[f*3], cy = xb[f*3+1], cz = xb[f*3+2];
      sc[0]=cx; sc[1]=cy; sc[2]=cz;
      float* nz = g_newxyz + (bk*NP+i)*3; nz[0]=cx; nz[1]=cy; nz[2]=cz;
      float* oa = outAgg + (bk*NP+i)*3;   oa[0]=cx; oa[1]=cy; oa[2]=cz;
    }
    __syncthreads();
    float cx = sc[0], cy = sc[1], cz = sc[2];
    float v = -1.f; int ix = 0;
#pragma unroll
    for (int j = 0; j < 4; j++){
      float d = d2f(px[j],py[j],pz[j], cx,cy,cz);
      dist[j] = fminf(dist[j], d);
      if (dist[j] > v){ v = dist[j]; ix = t + 256*j; }
    }
#pragma unroll
    for (int off=16; off; off>>=1){
      float ov = __shfl_down_sync(0xffffffffu, v, off);
      int   oi = __shfl_down_sync(0xffffffffu, ix, off);
      if (ov > v || (ov == v && oi < ix)){ v = ov; ix = oi; }
    }
    if (lane == 0){ sv[wp] = v; si_[wp] = ix; }
    __syncthreads();
    if (t < 8){
      v = sv[t]; ix = si_[t];
#pragma unroll
      for (int off=4; off; off>>=1){
        float ov = __shfl_down_sync(0xffu, v, off);
        int   oi = __shfl_down_sync(0xffu, ix, off);
        if (ov > v || (ov == v && oi < ix)){ v = ov; ix = oi; }
      }
      if (t == 0) sfar = ix;
    }
    __syncthreads();
  }
}

// fp16 MMA F1: A = features (via ldmatrix.trans from [c][m] fp16 tile), B = W1HF
__device__ void f1_body(const float* __restrict__ features, float* sm){
  u32*    W1s = (u32*)sm;            // [128][132] u32  (67584 B)
  __half* sF  = (__half*)(sm + 16896); // [64][136] halfs (17408 B)
  int fb = blockIdx.x - BKT;
  int bk = fb >> 3, mb = (fb & 7)*128;
  int b = bk / KK, k = bk % KK;
  int t = threadIdx.x;
  int w = t >> 5, lane = t & 31;
  int gid = lane >> 2, tig = lane & 3;
  int m0 = (w & 3)*32, n0 = (w >> 2)*64;
  int lg = lane >> 3, rr = lane & 7;

  // W1 resident in smem
  for (int i = t; i < 4224; i += 256)
    ((uint4*)W1s)[i] = ((const uint4*)g_W1HF)[i];

  u32 sFS = (u32)__cvta_generic_to_shared(sF);
  u32 W1S = (u32)__cvta_generic_to_shared(W1s);
  // A (trans, [c][m] storage): tile order (m-lo,k-lo)(m-hi,k-lo)(m-lo,k-hi)(m-hi,k-hi)
  u32 aOffH = (u32)(((lg >> 1)*8 + rr)*136 + m0 + (lg & 1)*8);
  // B: same recipe as k_group
  u32 bIdx  = (u32)((n0 + (lg >> 1)*8 + rr)*132 + (lg & 1)*4);

  float acc[2][8][4];
#pragma unroll
  for (int mt=0;mt<2;mt++)
#pragma unroll
    for (int nt=0;nt<8;nt++)
#pragma unroll
      for (int j=0;j<4;j++) acc[mt][nt][j] = 0.f;

  for (int c0 = 0; c0 < CC; c0 += 64){
    // features tile [64 c][128 m] -> fp16 smem (stride 136)
#pragma unroll
    for (int r8 = 0; r8 < 8; r8++){
      int e4 = r8*256 + t;
      int ci = e4 >> 5, m4 = (e4 & 31)*4;
      float4 v = *(const float4*)(features + ((size_t)(b*CC + c0 + ci)*KK + k)*MM + mb + m4);
      __half2* dst = (__half2*)(sF + ci*136 + m4);
      dst[0] = __floats2half2_rn(v.x, v.y);
      dst[1] = __floats2half2_rn(v.z, v.w);
    }
    __syncthreads();
#pragma unroll
    for (int ks = 0; ks < 4; ks++){
      u32 a[2][4];
      u32 abase = sFS + (aOffH + (u32)(ks*16*136))*2;
      ldsm_x4_t(a[0], abase);
      ldsm_x4_t(a[1], abase + 32);           // m +16 halfs = +32 B
      u32 kcol = (u32)((c0 >> 1) + ks*8);
#pragma unroll
      for (int pr = 0; pr < 4; pr++){
        u32 r[4];
        ldsm_x4(r, W1S + (bIdx + (u32)(pr*16*132) + kcol)*4);
        mma_f16(acc[0][2*pr],   a[0], &r[0]);
        mma_f16(acc[1][2*pr],   a[1], &r[0]);
        mma_f16(acc[0][2*pr+1], a[0], &r[2]);
        mma_f16(acc[1][2*pr+1], a[1], &r[2]);
      }
    }
    __syncthreads();
  }
  // store F1H (half2 pairs along o)
#pragma unroll
  for (int mt = 0; mt < 2; mt++){
    size_t row = (size_t)bk*MM + mb + m0 + mt*16 + gid;
#pragma unroll
    for (int nt = 0; nt < 8; nt++){
      int ch = (n0 + nt*8 + 2*tig) >> 1;
      g_F1H[row*64 + ch]     = h2pk(acc[mt][nt][0], acc[mt][nt][1]);
      g_F1H[(row+8)*64 + ch] = h2pk(acc[mt][nt][2], acc[mt][nt][3]);
    }
  }
}

__global__ __launch_bounds__(256) void k_fps_f1(const float* __restrict__ features,
                                                float* __restrict__ outAgg){
  extern __shared__ float smdyn[];
  if (blockIdx.x < BKT) fps_body(outAgg);
  else                  f1_body(features, smdyn);
}

// ---------------- launch 2: ball query ----------------
__global__ void k_ball(){
  int w = (blockIdx.x*blockDim.x + threadIdx.x) >> 5;
  int lane = threadIdx.x & 31;
  if (w >= BKT*NP) return;
  int bk = w / NP;
  const float* ctr = g_newxyz + w*3;
  float cx=ctr[0], cy=ctr[1], cz=ctr[2];
  const float R2 = (float)(0.15*0.15);
  int base = w*NS;
  int cnt = 0, first = 0;
  for (int ch = 0; ch < MM/32; ch++){
    int m = ch*32 + lane;
    const float* xp = g_x + (bk*MM + m)*3;
    float d = d2f(cx,cy,cz, xp[0],xp[1],xp[2]);
    unsigned mask = __ballot_sync(0xffffffffu, d < R2);
    if (cnt == 0 && mask) first = ch*32 + __ffs(mask) - 1;
    int pos = cnt + __popc(mask & ((1u<<lane)-1u));
    if ((d < R2) && pos < NS) g_gidx[base + pos] = m;
    cnt += __popc(mask);
    if (cnt >= NS) break;
  }
  for (int j = cnt + lane; j < NS; j += 32) g_gidx[base + j] = first;
}

// ---------------- launch 3 (PROFILED): persistent group, fp16 HMMA + ldmatrix ----
__global__ __launch_bounds__(256, 2) void k_group(float* __restrict__ outFeat){
  extern __shared__ u32 smu[];
  u32* W2u = smu;
  u32* W3u = smu + 128*68;
  u32* Hu  = smu + 2*128*68;
  __shared__ int   sIdx[NS];
  __shared__ float sCtr[3];
  __shared__ float sWx[3*128];
  __shared__ float sB1[128], sB2[128];

  int t = threadIdx.x;
  int w = t >> 5, lane = t & 31;
  int gid = lane >> 2, tig = lane & 3;
  int m0 = (w & 3)*32, n0 = (w >> 2)*64;

  int lg = lane >> 3, rr = lane & 7;
  u32 aIdx = (u32)((m0 + ((lg & 1) << 3) + rr)*68 + ((lg >> 1) << 2));
  u32 bIdx = (u32)((n0 + ((lg >> 1) << 3) + rr)*68 + ((lg & 1) << 2));

  u32 HuS  = (u32)__cvta_generic_to_shared(Hu);
  u32 W2S  = (u32)__cvta_generic_to_shared(W2u);
  u32 W3S  = (u32)__cvta_generic_to_shared(W3u);

  for (int i = t; i < 2176; i += 256){
    ((uint4*)W2u)[i] = ((const uint4*)g_W2H)[i];
    ((uint4*)W3u)[i] = ((const uint4*)g_W3H)[i];
  }
  for (int i = t; i < 384; i += 256) sWx[i] = g_W1x[i];
  if (t < 128){ sB1[t]=g_bM1[t]; sB2[t]=g_bM2[t]; }

  for (int gp = blockIdx.x; gp < NGRP; gp += gridDim.x){
    int bk = gp >> 7, p = gp & 127;
    if (t < NS) sIdx[t] = g_gidx[gp*NS + t];
    if (t < 3)  sCtr[t] = g_newxyz[gp*3 + t];
    __syncthreads();

    {
      int s = t >> 1, ob = (t & 1)*64;
      int m = sIdx[s];
      const float* xp = g_x + (bk*MM + m)*3;
      float gx = __fdiv_rn(__fsub_rn(xp[0], sCtr[0]), 0.15f);
      float gy = __fdiv_rn(__fsub_rn(xp[1], sCtr[1]), 0.15f);
      float gz = __fdiv_rn(__fsub_rn(xp[2], sCtr[2]), 0.15f);
      const uint4* fp = (const uint4*)(g_F1H + ((size_t)bk*MM + m)*64 + (ob>>1));
#pragma unroll
      for (int j4 = 0; j4 < 8; j4++){
        uint4 q = fp[j4];
        int o = ob + j4*8;
        float2 f0 = h2up(q.x), f1 = h2up(q.y), f2 = h2up(q.z), f3 = h2up(q.w);
        u32 ov[4];
        ov[0] = h2pk(fmaxf(f0.x + sWx[o]*gx   + sWx[128+o]*gy   + sWx[256+o]*gz   + sB1[o],   0.f),
                     fmaxf(f0.y + sWx[o+1]*gx + sWx[128+o+1]*gy + sWx[256+o+1]*gz + sB1[o+1], 0.f));
        ov[1] = h2pk(fmaxf(f1.x + sWx[o+2]*gx + sWx[128+o+2]*gy + sWx[256+o+2]*gz + sB1[o+2], 0.f),
                     fmaxf(f1.y + sWx[o+3]*gx + sWx[128+o+3]*gy + sWx[256+o+3]*gz + sB1[o+3], 0.f));
        ov[2] = h2pk(fmaxf(f2.x + sWx[o+4]*gx + sWx[128+o+4]*gy + sWx[256+o+4]*gz + sB1[o+4], 0.f),
                     fmaxf(f2.y + sWx[o+5]*gx + sWx[128+o+5]*gy + sWx[256+o+5]*gz + sB1[o+5], 0.f));
        ov[3] = h2pk(fmaxf(f3.x + sWx[o+6]*gx + sWx[128+o+6]*gy + sWx[256+o+6]*gz + sB1[o+6], 0.f),
                     fmaxf(f3.y + sWx[o+7]*gx + sWx[128+o+7]*gy + sWx[256+o+7]*gz + sB1[o+7], 0.f));
        *(uint4*)(Hu + s*68 + (ob>>1) + j4*4) = *(uint4*)ov;
      }
    }
    __syncthreads();

    float acc[2][8][4];

#pragma unroll
    for (int mt=0;mt<2;mt++)
#pragma unroll
      for (int nt=0;nt<8;nt++)
#pragma unroll
        for (int j=0;j<4;j++) acc[mt][nt][j] = 0.f;
#pragma unroll
    for (int ks = 0; ks < 8; ks++){
      u32 kb = (u32)(ks*8*4);
      u32 a[2][4];
      ldsm_x4(a[0], HuS + aIdx*4 + kb);
      ldsm_x4(a[1], HuS + (aIdx + 16*68)*4 + kb);
#pragma unroll
      for (int pr = 0; pr < 4; pr++){
        u32 r[4];
        ldsm_x4(r, W2S + (bIdx + (u32)(pr*16*68))*4 + kb);
        mma_f16(acc[0][2*pr],   a[0], &r[0]);
        mma_f16(acc[1][2*pr],   a[1], &r[0]);
        mma_f16(acc[0][2*pr+1], a[0], &r[2]);
        mma_f16(acc[1][2*pr+1], a[1], &r[2]);
      }
    }
    __syncthreads();

#pragma unroll
    for (int mt = 0; mt < 2; mt++){
      int r0 = m0 + mt*16 + gid;
#pragma unroll
      for (int nt = 0; nt < 8; nt++){
        int c0 = n0 + nt*8 + 2*tig;
        int ch = (c0 >> 1);
        float b0v = sB2[c0], b1v = sB2[c0+1];
        Hu[r0*68 + ch]     = h2pk(fmaxf(acc[mt][nt][0] + b0v, 0.f), fmaxf(acc[mt][nt][1] + b1v, 0.f));
        Hu[(r0+8)*68 + ch] = h2pk(fmaxf(acc[mt][nt][2] + b0v, 0.f), fmaxf(acc[mt][nt][3] + b1v, 0.f));
      }
    }
    __syncthreads();

#pragma unroll
    for (int mt=0;mt<2;mt++)
#pragma unroll
      for (int nt=0;nt<8;nt++)
#pragma unroll
        for (int j=0;j<4;j++) acc[mt][nt][j] = 0.f;
#pragma unroll
    for (int ks = 0; ks < 8; ks++){
      u32 kb = (u32)(ks*8*4);
      u32 a[2][4];
      ldsm_x4(a[0], HuS + aIdx*4 + kb);
      ldsm_x4(a[1], HuS + (aIdx + 16*68)*4 + kb);
#pragma unroll
      for (int pr = 0; pr < 4; pr++){
        u32 r[4];
        ldsm_x4(r, W3S + (bIdx + (u32)(pr*16*68))*4 + kb);
        mma_f16(acc[0][2*pr],   a[0], &r[0]);
        mma_f16(acc[1][2*pr],   a[1], &r[0]);
        mma_f16(acc[0][2*pr+1], a[0], &r[2]);
        mma_f16(acc[1][2*pr+1], a[1], &r[2]);
      }
    }

    float cm0[8], cm1[8];
#pragma unroll
    for (int nt = 0; nt < 8; nt++){
      cm0[nt] = fmaxf(fmaxf(acc[0][nt][0], acc[0][nt][2]), fmaxf(acc[1][nt][0], acc[1][nt][2]));
      cm1[nt] = fmaxf(fmaxf(acc[0][nt][1], acc[0][nt][3]), fmaxf(acc[1][nt][1], acc[1][nt][3]));
    }
#pragma unroll
    for (int off = 4; off < 32; off <<= 1){
#pragma unroll
      for (int nt = 0; nt < 8; nt++){
        cm0[nt] = fmaxf(cm0[nt], __shfl_xor_sync(0xffffffffu, cm0[nt], off));
        cm1[nt] = fmaxf(cm1[nt], __shfl_xor_sync(0xffffffffu, cm1[nt], off));
      }
    }
    __syncthreads();
    float* psm = (float*)Hu;
    if (gid == 0){
#pragma unroll
      for (int nt = 0; nt < 8; nt++){
        psm[(w & 3)*128 + n0 + nt*8 + 2*tig]     = cm0[nt];
        psm[(w & 3)*128 + n0 + nt*8 + 2*tig + 1] = cm1[nt];
      }
    }
    __syncthreads();
    if (t < 128){
      float mx = fmaxf(fmaxf(psm[t], psm[128+t]), fmaxf(psm[256+t], psm[384+t]));
      float res = fmaxf(mx + g_bM3[t], 0.f);
      int fo = (bk*128 + t)*NP + p;
      g_feat[fo] = res;
      outFeat[fo] = res;
    }
    __syncthreads();
  }
}

// ---------------- launch 4: c1 + c2 + head ----------------
__global__ __launch_bounds__(256) void k_c12h(const float* __restrict__ opw,
                                              const float* __restrict__ opb,
                                              float* __restrict__ outScores){
  extern __shared__ float sm[];
  float* sH = sm;
  float* sW = sm + 16384;
  __shared__ float sOp[5*128]; __shared__ float sOb[5];
  int bk = blockIdx.x, t = threadIdx.x;
  int k = bk % KK;
  for (int i = t; i < 640; i += 256) sOp[i] = opw[k*640 + i];
  if (t < 5) sOb[t] = opb[k*5 + t];
#pragma unroll
  for (int r = 0; r < 16; r++){
    ((float4*)sH)[r*256 + t] = ((const float4*)(g_feat + bk*16384))[r*256 + t];
    ((float4*)sW)[r*256 + t] = ((const float4*)g_C1T)[r*256 + t];
  }
  __syncthreads();
  int s0 = (t & 15)*8, o0 = (t >> 4)*8;
  u64 acc[8][4]; zacc8(acc);
  gemm8x8<128>(sH, sW, acc, s0, o0);
  float2 bb[4];
#pragma unroll
  for (int j = 0; j < 4; j++) bb[j] = *(const float2*)(g_bC1 + o0 + 2*j);
  __syncthreads();
#pragma unroll
  for (int si = 0; si < 8; si++)
#pragma unroll
    for (int j = 0; j < 4; j++){
      float2 v = upk(acc[si][j]);
      sH[(o0+2*j)*128 + s0+si]   = fmaxf(v.x + bb[j].x, 0.f);
      sH[(o0+2*j+1)*128 + s0+si] = fmaxf(v.y + bb[j].y, 0.f);
    }
#pragma unroll
  for (int r = 0; r < 16; r++) ((float4*)sW)[r*256 + t] = ((const float4*)g_C2T)[r*256 + t];
  __syncthreads();
  zacc8(acc);
  gemm8x8<128>(sH, sW, acc, s0, o0);
#pragma unroll
  for (int j = 0; j < 4; j++) bb[j] = *(const float2*)(g_bC2 + o0 + 2*j);
  __syncthreads();
#pragma unroll
  for (int si = 0; si < 8; si++)
#pragma unroll
    for (int j = 0; j < 4; j++){
      float2 v = upk(acc[si][j]);
      sH[(o0+2*j)*128 + s0+si]   = fmaxf(v.x + bb[j].x, 0.f);
      sH[(o0+2*j+1)*128 + s0+si] = fmaxf(v.y + bb[j].y, 0.f);
    }
  __syncthreads();
  if (t < 128){
    float a0=0,a1=0,a2=0,a3=0,a4=0;
#pragma unroll 4
    for (int c = 0; c < 128; c++){
      float nv = sH[c*128 + t];
      a0 += sOp[c]*nv; a1 += sOp[128+c]*nv; a2 += sOp[256+c]*nv; a3 += sOp[384+c]*nv; a4 += sOp[512+c]*nv;
    }
    a0+=sOb[0]; a1+=sOb[1]; a2+=sOb[2]; a3+=sOb[3]; a4+=sOb[4];
    const float* nz = g_newxyz + (bk*NP + t)*3;
    float* o = outScores + (bk*NP + t)*5;
    o[0]=a0; o[1]=a1; o[2]=nz[0]+a2; o[3]=nz[1]+a3; o[4]=nz[2]+a4;
  }
}

// ---------------- launcher ----------------
extern "C" void kernel_launch(void* const* d_in, const int* in_sizes, int n_in,
                              void* d_out, int out_size){
  (void)in_sizes; (void)n_in; (void)out_size;
  const float* xyz  = (const float*)d_in[0];
  const float* feats= (const float*)d_in[1];
  const float* m1_w = (const float*)d_in[2];
  const float* m1_b = (const float*)d_in[3];
  const float* m1_g = (const float*)d_in[4];
  const float* m1_be= (const float*)d_in[5];
  const float* m2_w = (const float*)d_in[6];
  const float* m2_b = (const float*)d_in[7];
  const float* m2_g = (const float*)d_in[8];
  const float* m2_be= (const float*)d_in[9];
  const float* m3_w = (const float*)d_in[10];
  const float* m3_b = (const float*)d_in[11];
  const float* m3_g = (const float*)d_in[12];
  const float* m3_be= (const float*)d_in[13];
  const float* c1_w = (const float*)d_in[14];
  const float* c1_b = (const float*)d_in[15];
  const float* c1_g = (const float*)d_in[16];
  const float* c1_be= (const float*)d_in[17];
  const float* c2_w = (const float*)d_in[18];
  const float* c2_b = (const float*)d_in[19];
  const float* c2_g = (const float*)d_in[20];
  const float* c2_be= (const float*)d_in[21];
  const float* op_w = (const float*)d_in[22];
  const float* op_b = (const float*)d_in[23];

  float* out = (float*)d_out;
  float* outScores = out;                 // 38*128*5
  float* outAgg    = out + 24320;         // 38*128*3
  float* outFeat   = out + 38912;         // 38*128*128

  const int GRP_SMEM = 3*128*68*4;        // 104448
  const int F1_SMEM  = (16896 + 4352)*4;  // 84992
  cudaFuncSetAttribute(k_fps_f1, cudaFuncAttributeMaxDynamicSharedMemorySize, F1_SMEM);
  cudaFuncSetAttribute(k_group,  cudaFuncAttributeMaxDynamicSharedMemorySize, GRP_SMEM);
  cudaFuncSetAttribute(k_c12h,   cudaFuncAttributeMaxDynamicSharedMemorySize, 131072);

  k_prep_fold<<<722, 256>>>(xyz, m1_w, m1_g, m2_w, m2_g,               // 0
      m3_w, m3_g, c1_w, c1_g, c2_w, c2_g,
      m1_b, m1_be, m2_b, m2_be, m3_b, m3_be, c1_b, c1_be, c2_b, c2_be);
  k_fps_f1<<<BKT + BKT*8, 256, F1_SMEM>>>(feats, outAgg);              // 1
  k_ball<<<(BKT*NP*32 + 255)/256, 256>>>();                            // 2
  k_group<<<296, 256, GRP_SMEM>>>(outFeat);                            // 3 <- profiled
  k_c12h<<<BKT, 256, 131072>>>(op_w, op_b, outScores);                 // 4
}